// round 12
// baseline (speedup 1.0000x reference)
#include <cuda_runtime.h>
#include <cuda_bf16.h>
#include <math.h>
#include <stdint.h>

// Problem constants
#define N_ROWS  32768
#define D_DIM   512
#define K_CODES 2048
#define HALFW   256

// Output layout
#define OFF_QOUT 1
#define OFF_PERP (1 + N_ROWS * D_DIM)
#define OFF_ENC  (2 + N_ROWS * D_DIM)   // 8-byte aligned only

#define MARGIN1 0.30f
#define MARGIN2 0.02f
#define MAXF    8192

// Scratch
__device__ float         g_h[(size_t)N_ROWS * D_DIM];
__device__ __nv_bfloat16 g_hhi[(size_t)N_ROWS * D_DIM];
__device__ __nv_bfloat16 g_hlo[(size_t)N_ROWS * D_DIM];
__device__ __nv_bfloat16 g_ehi[(size_t)K_CODES * D_DIM];
__device__ __nv_bfloat16 g_elo[(size_t)K_CODES * D_DIM];
__device__ __nv_bfloat16 g_x1[(size_t)N_ROWS * D_DIM];
__device__ __nv_bfloat16 g_x2[(size_t)N_ROWS * D_DIM];
__device__ __nv_bfloat16 g_w1[(size_t)D_DIM * D_DIM];
__device__ __nv_bfloat16 g_w2[(size_t)D_DIM * D_DIM];
__device__ __nv_bfloat16 g_fhi[(size_t)MAXF * D_DIM];
__device__ __nv_bfloat16 g_flo[(size_t)MAXF * D_DIM];
__device__ unsigned long long g_p2k[(size_t)MAXF * 16];
__device__ float g_p2v[(size_t)MAXF * 16];
__device__ float g_en[K_CODES];
__device__ int   g_idx[N_ROWS];
__device__ float g_partial[N_ROWS];
__device__ int   g_counts[K_CODES];
__device__ int   g_nflag;
__device__ int   g_flagged[N_ROWS];
__device__ int   g_nflag1;
__device__ int   g_flag1[N_ROWS];
__device__ unsigned long long g_best[N_ROWS];

// ---------------------------------------------------------------------------
// PTX helpers
// ---------------------------------------------------------------------------
__device__ __forceinline__ void mma16816(float* c, const uint32_t* a, const uint32_t* b) {
    asm volatile(
        "mma.sync.aligned.m16n8k16.row.col.f32.bf16.bf16.f32 "
        "{%0,%1,%2,%3}, {%4,%5,%6,%7}, {%8,%9}, {%0,%1,%2,%3};"
        : "+f"(c[0]), "+f"(c[1]), "+f"(c[2]), "+f"(c[3])
        : "r"(a[0]), "r"(a[1]), "r"(a[2]), "r"(a[3]), "r"(b[0]), "r"(b[1]));
}
__device__ __forceinline__ void ldsm_x4(uint32_t* r, uint32_t addr) {
    asm volatile("ldmatrix.sync.aligned.m8n8.x4.shared.b16 {%0,%1,%2,%3}, [%4];"
                 : "=r"(r[0]), "=r"(r[1]), "=r"(r[2]), "=r"(r[3]) : "r"(addr));
}
__device__ __forceinline__ void cp16(uint32_t dst_smem, const void* src) {
    asm volatile("cp.async.cg.shared.global [%0], [%1], 16;" :: "r"(dst_smem), "l"(src));
}
#define CP_COMMIT() asm volatile("cp.async.commit_group;" ::: "memory")
#define CP_WAIT(N)  asm volatile("cp.async.wait_group %0;" :: "n"(N) : "memory")

__device__ __forceinline__ uint32_t fmap(float f) {
    uint32_t u = __float_as_uint(f);
    return (u & 0x80000000u) ? ~u : (u | 0x80000000u);
}
__device__ __forceinline__ float funmap(uint32_t m) {
    return (m & 0x80000000u) ? __uint_as_float(m ^ 0x80000000u) : __uint_as_float(~m);
}

#define SPITCH 72
// Wide-tile kernels (gemm1/pass1): A 128 rows + B 256 rows per stage
#define WSTAGE_A (128 * SPITCH * 2)                // 18432
#define WSTAGE_B (256 * SPITCH * 2)                // 36864
#define WSTAGE   (WSTAGE_A + WSTAGE_B)             // 55296
#define WRING    (2 * WSTAGE)                      // 110592
// pass2 (old shape)
#define STAGE_BYTES (128 * SPITCH * 2)
#define RING_BYTES  (2 * 2 * STAGE_BYTES)

// ---------------------------------------------------------------------------
// prep kernels
// ---------------------------------------------------------------------------
__global__ void prep_x_kernel(const float* __restrict__ x0, const float* __restrict__ x1)
{
    const size_t i = ((size_t)blockIdx.x * 256 + threadIdx.x) * 4;
    const int col = (int)(i & (D_DIM - 1));
    const size_t row = i >> 9;
    const float* src = (col < HALFW) ? (x0 + row * HALFW + col)
                                     : (x1 + row * HALFW + (col - HALFW));
    float4 v = *(const float4*)src;
    float e[4] = {v.x, v.y, v.z, v.w};
    __nv_bfloat16 a[4], b[4];
#pragma unroll
    for (int j = 0; j < 4; j++) {
        a[j] = __float2bfloat16_rn(e[j]);
        b[j] = __float2bfloat16_rn(e[j] - __bfloat162float(a[j]));
    }
    *(__nv_bfloat162*)(g_x1 + i)     = __nv_bfloat162(a[0], a[1]);
    *(__nv_bfloat162*)(g_x1 + i + 2) = __nv_bfloat162(a[2], a[3]);
    *(__nv_bfloat162*)(g_x2 + i)     = __nv_bfloat162(b[0], b[1]);
    *(__nv_bfloat162*)(g_x2 + i + 2) = __nv_bfloat162(b[2], b[3]);
}

__global__ void prep_w_kernel(const float* __restrict__ W)
{
    const size_t i = ((size_t)blockIdx.x * 256 + threadIdx.x) * 4;
    float4 v = *(const float4*)(W + i);
    float e[4] = {v.x, v.y, v.z, v.w};
    __nv_bfloat16 a[4], b[4];
#pragma unroll
    for (int j = 0; j < 4; j++) {
        a[j] = __float2bfloat16_rn(e[j]);
        b[j] = __float2bfloat16_rn(e[j] - __bfloat162float(a[j]));
    }
    *(__nv_bfloat162*)(g_w1 + i)     = __nv_bfloat162(a[0], a[1]);
    *(__nv_bfloat162*)(g_w1 + i + 2) = __nv_bfloat162(a[2], a[3]);
    *(__nv_bfloat162*)(g_w2 + i)     = __nv_bfloat162(b[0], b[1]);
    *(__nv_bfloat162*)(g_w2 + i + 2) = __nv_bfloat162(b[2], b[3]);
}

__global__ void prep_emb_kernel(const float* __restrict__ emb)
{
    __shared__ float red[128];
    const int k   = blockIdx.x;
    const int tid = threadIdx.x;
    const size_t base = (size_t)k * D_DIM + tid * 4;
    float4 v = *(const float4*)(emb + base);
    red[tid] = v.x * v.x + v.y * v.y + v.z * v.z + v.w * v.w;

    __nv_bfloat16 hx = __float2bfloat16_rn(v.x), hy = __float2bfloat16_rn(v.y);
    __nv_bfloat16 hz = __float2bfloat16_rn(v.z), hw = __float2bfloat16_rn(v.w);
    __nv_bfloat16 lx = __float2bfloat16_rn(v.x - __bfloat162float(hx));
    __nv_bfloat16 ly = __float2bfloat16_rn(v.y - __bfloat162float(hy));
    __nv_bfloat16 lz = __float2bfloat16_rn(v.z - __bfloat162float(hz));
    __nv_bfloat16 lw = __float2bfloat16_rn(v.w - __bfloat162float(hw));
    *(__nv_bfloat162*)(g_ehi + base)     = __nv_bfloat162(hx, hy);
    *(__nv_bfloat162*)(g_ehi + base + 2) = __nv_bfloat162(hz, hw);
    *(__nv_bfloat162*)(g_elo + base)     = __nv_bfloat162(lx, ly);
    *(__nv_bfloat162*)(g_elo + base + 2) = __nv_bfloat162(lz, lw);

    __syncthreads();
    for (int off = 64; off; off >>= 1) {
        if (tid < off) red[tid] += red[tid + off];
        __syncthreads();
    }
    if (tid == 0) {
        g_en[k] = red[0];
        g_counts[k] = 0;
        if (k == 0) { g_nflag = 0; g_nflag1 = 0; }
    }
}

// ===========================================================================
// WIDE TILE (1 CTA/SM): CTA 128x256, warp tile 64x64 (acc 128 regs)
// ===========================================================================
// Per-ks fragments: A 4 x ldsm_x4, B 4 x ldsm_x4 -> 32 MMAs
#define WIDE_COMPUTE(acc, sAu, sBu, aoff, boff) do { \
    _Pragma("unroll") \
    for (int ks = 0; ks < 4; ks++) { \
        uint32_t bfr[8][2]; \
        _Pragma("unroll") \
        for (int p = 0; p < 4; p++) { \
            uint32_t t[4]; \
            ldsm_x4(t, sBu + boff[p] + ks * 32); \
            bfr[2*p][0] = t[0];   bfr[2*p][1] = t[1]; \
            bfr[2*p+1][0] = t[2]; bfr[2*p+1][1] = t[3]; \
        } \
        _Pragma("unroll") \
        for (int mt = 0; mt < 4; mt++) { \
            uint32_t afr[4]; \
            ldsm_x4(afr, sAu + aoff[mt] + ks * 32); \
            _Pragma("unroll") \
            for (int nn = 0; nn < 8; nn++) \
                mma16816(acc[mt][nn], afr, bfr[nn]); \
        } \
    } \
} while (0)

// ---------------------------------------------------------------------------
// GEMM1 wide: 3-phase, CTA 128x256, grid (2, 256)
// ---------------------------------------------------------------------------
#define NSTEP1 24

__global__ __launch_bounds__(256, 1)
void gemm1_mma_kernel(const float* __restrict__ bias)
{
    extern __shared__ __align__(16) char dsm[];
    const uint32_t smem_u32 = (uint32_t)__cvta_generic_to_shared(dsm);

    const int tid  = threadIdx.x;
    const int lane = tid & 31;
    const int w    = tid >> 5;
    const int wm   = w >> 2;        // 0..1
    const int wn   = w & 3;         // 0..3
    const int lq   = lane >> 2;
    const int lr   = lane & 3;
    const int m0   = blockIdx.y * 128;
    const int n0   = blockIdx.x * 256;

    const int lrow0 = tid >> 3;     // 0..31
    const int lch   = tid & 7;

    const int arow  = (lane < 16) ? lane : (lane - 16);
    const int acol8 = (lane < 16) ? 0 : 8;
    uint32_t aoff[4];
#pragma unroll
    for (int mt = 0; mt < 4; mt++)
        aoff[mt] = (uint32_t)(((wm * 64 + mt * 16 + arow) * SPITCH + acol8) * 2);
    const int bg = lane >> 3;
    uint32_t boff[4];
#pragma unroll
    for (int p = 0; p < 4; p++) {
        int nrow = wn * 64 + (2 * p + (bg >> 1)) * 8 + (lane & 7);
        boff[p] = (uint32_t)((nrow * SPITCH + (bg & 1) * 8) * 2);
    }

    auto load_step = [&](int step, int stage) {
        const int phase = step >> 3;
        const int kk    = (step & 7) * 64;
        const __nv_bfloat16* Ag = (phase < 2) ? g_x1 : g_x2;
        const __nv_bfloat16* Bg = (phase == 1) ? g_w2 : g_w1;
        uint32_t sAb = smem_u32 + stage * WSTAGE;
        uint32_t sBb = sAb + WSTAGE_A;
#pragma unroll
        for (int i = 0; i < 4; i++) {          // A: 128 rows
            int r = lrow0 + i * 32;
            cp16(sAb + (uint32_t)((r * SPITCH + lch * 8) * 2),
                 Ag + (size_t)(m0 + r) * D_DIM + kk + lch * 8);
        }
#pragma unroll
        for (int i = 0; i < 8; i++) {          // B: 256 rows
            int r = lrow0 + i * 32;
            cp16(sBb + (uint32_t)((r * SPITCH + lch * 8) * 2),
                 Bg + (size_t)(n0 + r) * D_DIM + kk + lch * 8);
        }
    };

    float acc[4][8][4];
#pragma unroll
    for (int a = 0; a < 4; a++)
#pragma unroll
        for (int b = 0; b < 8; b++)
#pragma unroll
            for (int c = 0; c < 4; c++) acc[a][b][c] = 0.0f;

    load_step(0, 0);
    CP_COMMIT();

    for (int cur = 0; cur < NSTEP1; cur++) {
        CP_WAIT(0);
        __syncthreads();
        if (cur + 1 < NSTEP1) {
            load_step(cur + 1, (cur + 1) & 1);
            CP_COMMIT();
        }
        const uint32_t sAu = smem_u32 + (uint32_t)((cur & 1) * WSTAGE);
        const uint32_t sBu = sAu + WSTAGE_A;
        WIDE_COMPUTE(acc, sAu, sBu, aoff, boff);
    }

    // epilogue: bias + h fp32 + hi/lo splits
#pragma unroll
    for (int mt = 0; mt < 4; mt++) {
#pragma unroll
        for (int half = 0; half < 2; half++) {
            const int row = m0 + wm * 64 + mt * 16 + half * 8 + lq;
#pragma unroll
            for (int nn = 0; nn < 8; nn++) {
                const int col = n0 + wn * 64 + nn * 8 + lr * 2;
                float h0 = acc[mt][nn][half * 2 + 0] + bias[col];
                float h1 = acc[mt][nn][half * 2 + 1] + bias[col + 1];
                const size_t o = (size_t)row * D_DIM + col;
                *(float2*)(g_h + o) = make_float2(h0, h1);
                __nv_bfloat16 p0 = __float2bfloat16_rn(h0);
                __nv_bfloat16 p1 = __float2bfloat16_rn(h1);
                __nv_bfloat16 q0 = __float2bfloat16_rn(h0 - __bfloat162float(p0));
                __nv_bfloat16 q1 = __float2bfloat16_rn(h1 - __bfloat162float(p1));
                *(__nv_bfloat162*)(g_hhi + o) = __nv_bfloat162(p0, p1);
                *(__nv_bfloat162*)(g_hlo + o) = __nv_bfloat162(q0, q1);
            }
        }
    }
}

// ---------------------------------------------------------------------------
// GEMM2 pass 1 wide: single-phase bf16, K=512, CTA 128 rows x N-tiles of 256.
// ---------------------------------------------------------------------------
#define NSTEP_P1 64   // 8 nt * 8 kk

__global__ __launch_bounds__(256, 1)
void gemm2_pass1_kernel()
{
    extern __shared__ __align__(16) char dsm[];
    const uint32_t smem_u32 = (uint32_t)__cvta_generic_to_shared(dsm);

    const int tid  = threadIdx.x;
    const int lane = tid & 31;
    const int w    = tid >> 5;
    const int wm   = w >> 2;
    const int wn   = w & 3;
    const int lq   = lane >> 2;
    const int lr   = lane & 3;
    const int m0   = blockIdx.x * 128;

    const int lrow0 = tid >> 3;
    const int lch   = tid & 7;

    const int arow  = (lane < 16) ? lane : (lane - 16);
    const int acol8 = (lane < 16) ? 0 : 8;
    uint32_t aoff[4];
#pragma unroll
    for (int mt = 0; mt < 4; mt++)
        aoff[mt] = (uint32_t)(((wm * 64 + mt * 16 + arow) * SPITCH + acol8) * 2);
    const int bg = lane >> 3;
    uint32_t boff[4];
#pragma unroll
    for (int p = 0; p < 4; p++) {
        int nrow = wn * 64 + (2 * p + (bg >> 1)) * 8 + (lane & 7);
        boff[p] = (uint32_t)((nrow * SPITCH + (bg & 1) * 8) * 2);
    }

    float v1[8], v2[8]; int i1[8];
#pragma unroll
    for (int s = 0; s < 8; s++) { v1[s] = 3.4e38f; v2[s] = 3.4e38f; i1[s] = 0; }

#define UPD(sl, cc, ss) do { float _s = (ss); \
    if (_s < v1[sl]) { v2[sl] = v1[sl]; v1[sl] = _s; i1[sl] = (cc); } \
    else if (_s < v2[sl]) v2[sl] = _s; } while (0)

    auto load_step = [&](int step, int stage) {
        const int nt = step >> 3;
        const int kk = (step & 7) * 64;
        const int n0 = nt * 256;
        uint32_t sAb = smem_u32 + stage * WSTAGE;
        uint32_t sBb = sAb + WSTAGE_A;
#pragma unroll
        for (int i = 0; i < 4; i++) {
            int r = lrow0 + i * 32;
            cp16(sAb + (uint32_t)((r * SPITCH + lch * 8) * 2),
                 g_hhi + (size_t)(m0 + r) * D_DIM + kk + lch * 8);
        }
#pragma unroll
        for (int i = 0; i < 8; i++) {
            int r = lrow0 + i * 32;
            cp16(sBb + (uint32_t)((r * SPITCH + lch * 8) * 2),
                 g_ehi + (size_t)(n0 + r) * D_DIM + kk + lch * 8);
        }
    };

    load_step(0, 0);
    CP_COMMIT();

    float acc[4][8][4];
    for (int nt = 0; nt < 8; nt++) {
        const int n0 = nt * 256;
#pragma unroll
        for (int a = 0; a < 4; a++)
#pragma unroll
            for (int b = 0; b < 8; b++)
#pragma unroll
                for (int c = 0; c < 4; c++) acc[a][b][c] = 0.0f;

        for (int vc = 0; vc < 8; vc++) {
            const int cur = nt * 8 + vc;
            CP_WAIT(0);
            __syncthreads();
            if (cur + 1 < NSTEP_P1) {
                load_step(cur + 1, (cur + 1) & 1);
                CP_COMMIT();
            }
            const uint32_t sAu = smem_u32 + (uint32_t)((cur & 1) * WSTAGE);
            const uint32_t sBu = sAu + WSTAGE_A;
            WIDE_COMPUTE(acc, sAu, sBu, aoff, boff);
        }

#pragma unroll
        for (int mt = 0; mt < 4; mt++) {
#pragma unroll
            for (int nn = 0; nn < 8; nn++) {
                const int col = n0 + wn * 64 + nn * 8 + lr * 2;
                const float e0 = g_en[col], e1 = g_en[col + 1];
                const int s0 = mt * 2, s1 = mt * 2 + 1;
                UPD(s0, col,     e0 - 2.0f * acc[mt][nn][0]);
                UPD(s0, col + 1, e1 - 2.0f * acc[mt][nn][1]);
                UPD(s1, col,     e0 - 2.0f * acc[mt][nn][2]);
                UPD(s1, col + 1, e1 - 2.0f * acc[mt][nn][3]);
            }
        }
    }

#pragma unroll
    for (int off = 1; off <= 2; off <<= 1) {
#pragma unroll
        for (int sl = 0; sl < 8; sl++) {
            float ov1 = __shfl_xor_sync(0xffffffffu, v1[sl], off);
            int   oi1 = __shfl_xor_sync(0xffffffffu, i1[sl], off);
            float ov2 = __shfl_xor_sync(0xffffffffu, v2[sl], off);
            if (ov1 < v1[sl] || (ov1 == v1[sl] && oi1 < i1[sl])) {
                v2[sl] = fminf(v1[sl], ov2); v1[sl] = ov1; i1[sl] = oi1;
            } else {
                v2[sl] = fminf(v2[sl], ov1);
            }
        }
    }

    __syncthreads();
    float* rv1 = (float*)dsm;
    int*   ri1 = (int*)(dsm + 2048);
    float* rv2 = (float*)(dsm + 4096);
    if (lr == 0) {
#pragma unroll
        for (int sl = 0; sl < 8; sl++) {
            int row = wm * 64 + (sl >> 1) * 16 + (sl & 1) * 8 + lq;
            rv1[row * 4 + wn] = v1[sl];
            ri1[row * 4 + wn] = i1[sl];
            rv2[row * 4 + wn] = v2[sl];
        }
    }
    __syncthreads();
    if (tid < 128) {
        float bv1 = rv1[tid * 4]; int bi1 = ri1[tid * 4]; float bv2 = rv2[tid * 4];
#pragma unroll
        for (int j = 1; j < 4; j++) {
            float ov1 = rv1[tid * 4 + j]; int oi1 = ri1[tid * 4 + j]; float ov2 = rv2[tid * 4 + j];
            if (ov1 < bv1 || (ov1 == bv1 && oi1 < bi1)) {
                bv2 = fminf(bv1, ov2); bv1 = ov1; bi1 = oi1;
            } else {
                bv2 = fminf(bv2, ov1);
            }
        }
        const int row = m0 + tid;
        g_idx[row] = bi1;
        if (bv2 - bv1 <= MARGIN1) {
            int slot = atomicAdd(&g_nflag1, 1);
            if (slot < MAXF) g_flag1[slot] = row;
        }
    }
}

// ---------------------------------------------------------------------------
// gather flagged rows
// ---------------------------------------------------------------------------
__global__ __launch_bounds__(128)
void gather_kernel()
{
    const int cnt = min(g_nflag1, MAXF);
    const int tid = threadIdx.x;
    for (int f = blockIdx.x; f < cnt; f += gridDim.x) {
        const int row = g_flag1[f];
        const uint32_t* shi = (const uint32_t*)(g_hhi + (size_t)row * D_DIM);
        const uint32_t* slo = (const uint32_t*)(g_hlo + (size_t)row * D_DIM);
        uint32_t* dhi = (uint32_t*)(g_fhi + (size_t)f * D_DIM);
        uint32_t* dlo = (uint32_t*)(g_flo + (size_t)f * D_DIM);
        dhi[tid * 2] = shi[tid * 2]; dhi[tid * 2 + 1] = shi[tid * 2 + 1];
        dlo[tid * 2] = slo[tid * 2]; dlo[tid * 2 + 1] = slo[tid * 2 + 1];
    }
}

// ---------------------------------------------------------------------------
// pass 2 (old shape: 2 CTA/SM, warp tile 64x32)
// ---------------------------------------------------------------------------
struct Frags { uint32_t a[4][4]; uint32_t b[4][2]; };

__device__ __forceinline__ void load_frags(Frags& F, int ks, uint32_t sAu, uint32_t sBu,
                                           const uint32_t* aoff, const uint32_t* boff) {
    uint32_t t0[4], t1[4];
    ldsm_x4(t0, sBu + boff[0] + ks * 32);
    ldsm_x4(t1, sBu + boff[1] + ks * 32);
    F.b[0][0] = t0[0]; F.b[0][1] = t0[1];
    F.b[1][0] = t0[2]; F.b[1][1] = t0[3];
    F.b[2][0] = t1[0]; F.b[2][1] = t1[1];
    F.b[3][0] = t1[2]; F.b[3][1] = t1[3];
#pragma unroll
    for (int mt = 0; mt < 4; mt++)
        ldsm_x4(F.a[mt], sAu + aoff[mt] + ks * 32);
}

__global__ __launch_bounds__(256, 2)
void gemm2_pass2_kernel()
{
    const int cnt = min(g_nflag1, MAXF);
    const int rt = blockIdx.x >> 4;
    const int nt = blockIdx.x & 15;
    if (rt * 128 >= cnt) return;

    extern __shared__ __align__(16) char dsm[];
    const uint32_t smem_u32 = (uint32_t)__cvta_generic_to_shared(dsm);

    const int tid  = threadIdx.x;
    const int lane = tid & 31;
    const int w    = tid >> 5;
    const int wm   = w >> 2;
    const int wn   = w & 3;
    const int lq   = lane >> 2;
    const int lr   = lane & 3;
    const int f0   = rt * 128;
    const int n0   = nt * 128;

    const int lrow0 = tid >> 3;
    const int lch   = tid & 7;

    const int arow  = (lane < 16) ? lane : (lane - 16);
    const int acol8 = (lane < 16) ? 0 : 8;
    uint32_t aoff[4];
#pragma unroll
    for (int mt = 0; mt < 4; mt++)
        aoff[mt] = (uint32_t)(((wm * 64 + mt * 16 + arow) * SPITCH + acol8) * 2);
    const int bg = lane >> 3;
    uint32_t boff[2];
#pragma unroll
    for (int p = 0; p < 2; p++) {
        int nrow = wn * 32 + (2 * p + (bg >> 1)) * 8 + (lane & 7);
        boff[p] = (uint32_t)((nrow * SPITCH + (bg & 1) * 8) * 2);
    }

    auto load_step = [&](int step, int stage) {
        const int phase = step >> 3;
        const int kk    = (step & 7) * 64;
        const __nv_bfloat16* Ag = (phase < 2)  ? g_fhi : g_flo;
        const __nv_bfloat16* Bg = (phase == 1) ? g_elo : g_ehi;
        uint32_t sAb = smem_u32 + stage * 2 * STAGE_BYTES;
        uint32_t sBb = sAb + STAGE_BYTES;
#pragma unroll
        for (int i = 0; i < 4; i++) {
            int r = lrow0 + i * 32;
            cp16(sAb + (uint32_t)((r * SPITCH + lch * 8) * 2),
                 Ag + (size_t)(f0 + r) * D_DIM + kk + lch * 8);
            cp16(sBb + (uint32_t)((r * SPITCH + lch * 8) * 2),
                 Bg + (size_t)(n0 + r) * D_DIM + kk + lch * 8);
        }
    };

    float acc[4][4][4];
#pragma unroll
    for (int a = 0; a < 4; a++)
#pragma unroll
        for (int b = 0; b < 4; b++)
#pragma unroll
            for (int c = 0; c < 4; c++) acc[a][b][c] = 0.0f;

    load_step(0, 0);
    CP_COMMIT();

    for (int cur = 0; cur < 24; cur++) {
        CP_WAIT(0);
        __syncthreads();
        if (cur + 1 < 24) {
            load_step(cur + 1, (cur + 1) & 1);
            CP_COMMIT();
        }
        const uint32_t sAu = smem_u32 + (uint32_t)((cur & 1) * 2 * STAGE_BYTES);
        const uint32_t sBu = sAu + STAGE_BYTES;
        Frags F;
#pragma unroll
        for (int ks = 0; ks < 4; ks++) {
            load_frags(F, ks, sAu, sBu, aoff, boff);
#pragma unroll
            for (int mt = 0; mt < 4; mt++)
#pragma unroll
                for (int nn = 0; nn < 4; nn++)
                    mma16816(acc[mt][nn], F.a[mt], F.b[nn]);
        }
    }

    float v1[8], v2[8]; int i1[8];
#pragma unroll
    for (int s = 0; s < 8; s++) { v1[s] = 3.4e38f; v2[s] = 3.4e38f; i1[s] = 0; }
#pragma unroll
    for (int mt = 0; mt < 4; mt++) {
#pragma unroll
        for (int nn = 0; nn < 4; nn++) {
            const int col = n0 + wn * 32 + nn * 8 + lr * 2;
            const float e0 = g_en[col], e1 = g_en[col + 1];
            const int s0 = mt * 2, s1 = mt * 2 + 1;
            UPD(s0, col,     e0 - 2.0f * acc[mt][nn][0]);
            UPD(s0, col + 1, e1 - 2.0f * acc[mt][nn][1]);
            UPD(s1, col,     e0 - 2.0f * acc[mt][nn][2]);
            UPD(s1, col + 1, e1 - 2.0f * acc[mt][nn][3]);
        }
    }

#pragma unroll
    for (int off = 1; off <= 2; off <<= 1) {
#pragma unroll
        for (int sl = 0; sl < 8; sl++) {
            float ov1 = __shfl_xor_sync(0xffffffffu, v1[sl], off);
            int   oi1 = __shfl_xor_sync(0xffffffffu, i1[sl], off);
            float ov2 = __shfl_xor_sync(0xffffffffu, v2[sl], off);
            if (ov1 < v1[sl] || (ov1 == v1[sl] && oi1 < i1[sl])) {
                v2[sl] = fminf(v1[sl], ov2); v1[sl] = ov1; i1[sl] = oi1;
            } else {
                v2[sl] = fminf(v2[sl], ov1);
            }
        }
    }

    __syncthreads();
    float* rv1 = (float*)dsm;
    int*   ri1 = (int*)(dsm + 2048);
    float* rv2 = (float*)(dsm + 4096);
    if (lr == 0) {
#pragma unroll
        for (int sl = 0; sl < 8; sl++) {
            int row = wm * 64 + (sl >> 1) * 16 + (sl & 1) * 8 + lq;
            rv1[row * 4 + wn] = v1[sl];
            ri1[row * 4 + wn] = i1[sl];
            rv2[row * 4 + wn] = v2[sl];
        }
    }
    __syncthreads();
    if (tid < 128) {
        float bv1 = rv1[tid * 4]; int bi1 = ri1[tid * 4]; float bv2 = rv2[tid * 4];
#pragma unroll
        for (int j = 1; j < 4; j++) {
            float ov1 = rv1[tid * 4 + j]; int oi1 = ri1[tid * 4 + j]; float ov2 = rv2[tid * 4 + j];
            if (ov1 < bv1 || (ov1 == bv1 && oi1 < bi1)) {
                bv2 = fminf(bv1, ov2); bv1 = ov1; bi1 = oi1;
            } else {
                bv2 = fminf(bv2, ov1);
            }
        }
        const int crow = f0 + tid;
        g_p2k[(size_t)crow * 16 + nt] =
            ((unsigned long long)fmap(bv1) << 32) | (unsigned)bi1;
        g_p2v[(size_t)crow * 16 + nt] = bv2;
    }
}

// ---------------------------------------------------------------------------
// combine
// ---------------------------------------------------------------------------
__global__ __launch_bounds__(256)
void combine_kernel()
{
    const int cnt = min(g_nflag1, MAXF);
    for (int f = blockIdx.x * 256 + threadIdx.x; f < cnt; f += gridDim.x * 256) {
        unsigned long long bestk = 0xFFFFFFFFFFFFFFFFull;
#pragma unroll
        for (int j = 0; j < 16; j++)
            bestk = min(bestk, g_p2k[(size_t)f * 16 + j]);
        float s1 = funmap((uint32_t)(bestk >> 32));
        float s2 = 3.4e38f;
#pragma unroll
        for (int j = 0; j < 16; j++) {
            unsigned long long k = g_p2k[(size_t)f * 16 + j];
            float v2 = g_p2v[(size_t)f * 16 + j];
            if (k != bestk) s2 = fminf(s2, funmap((uint32_t)(k >> 32)));
            s2 = fminf(s2, v2);
        }
        const int orig = g_flag1[f];
        if (s2 - s1 <= MARGIN2) {
            g_idx[orig]  = -1;
            g_best[orig] = 0xFFFFFFFFFFFFFFFFull;
            int slot = atomicAdd(&g_nflag, 1);
            g_flagged[slot] = orig;
        } else {
            g_idx[orig] = (int)(bestk & 0xFFFFFFFFull);
        }
    }
}

// ---------------------------------------------------------------------------
// Exact fp32 fallback
// ---------------------------------------------------------------------------
__global__ __launch_bounds__(256)
void fallback_kernel(const float* __restrict__ emb)
{
    __shared__ float hrow[D_DIM];
    const int tid = threadIdx.x;
    const int cnt = g_nflag;
    const int total = cnt * 8;

    for (int wk = blockIdx.x; wk < total; wk += gridDim.x) {
        const int f     = wk >> 3;
        const int chunk = wk & 7;
        const int row   = g_flagged[f];

        if (tid < 128)
            *(float4*)(hrow + tid * 4) = *(const float4*)(g_h + (size_t)row * D_DIM + tid * 4);
        __syncthreads();

        const int k = chunk * 256 + tid;
        const float4* ep = (const float4*)(emb + (size_t)k * D_DIM);
        float a0 = 0.f, a1 = 0.f, a2 = 0.f, a3 = 0.f;
#pragma unroll 16
        for (int d4 = 0; d4 < D_DIM / 4; d4++) {
            float4 e = ep[d4];
            float4 h = *(const float4*)(hrow + d4 * 4);
            a0 += e.x * h.x; a1 += e.y * h.y; a2 += e.z * h.z; a3 += e.w * h.w;
        }
        float s = g_en[k] - 2.0f * ((a0 + a1) + (a2 + a3));
        unsigned long long key = ((unsigned long long)fmap(s) << 32) | (unsigned)k;
        atomicMin(&g_best[row], key);
        __syncthreads();
    }
}

// ---------------------------------------------------------------------------
// Epilogue
// ---------------------------------------------------------------------------
__global__ void epilogue_kernel(const float* __restrict__ emb, float* __restrict__ out)
{
    __shared__ float red[128];
    const int n   = blockIdx.x;
    const int tid = threadIdx.x;
    int idx = g_idx[n];
    if (idx < 0) idx = (int)(g_best[n] & 0xFFFFFFFFull);

    float4 hv = *(const float4*)(g_h + (size_t)n * D_DIM + tid * 4);
    float4 qv = *(const float4*)(emb + (size_t)idx * D_DIM + tid * 4);
    float d0 = qv.x - hv.x, d1 = qv.y - hv.y, d2 = qv.z - hv.z, d3 = qv.w - hv.w;

    float* qo = out + OFF_QOUT + (size_t)n * D_DIM + tid * 4;
    __stcs(qo + 0, hv.x + d0);
    __stcs(qo + 1, hv.y + d1);
    __stcs(qo + 2, hv.z + d2);
    __stcs(qo + 3, hv.w + d3);

    red[tid] = d0 * d0 + d1 * d1 + d2 * d2 + d3 * d3;

    float2* er2 = (float2*)(out + OFF_ENC + (size_t)n * K_CODES);
    const int unit = idx >> 1, comp = idx & 1;
#pragma unroll
    for (int i = 0; i < 8; i++) {
        int u = tid + i * 128;
        float2 v = make_float2(0.0f, 0.0f);
        if (u == unit) { if (comp == 0) v.x = 1.0f; else v.y = 1.0f; }
        __stcs(er2 + u, v);
    }

    __syncthreads();
    for (int off = 64; off; off >>= 1) {
        if (tid < off) red[tid] += red[tid + off];
        __syncthreads();
    }
    if (tid == 0) {
        g_partial[n] = red[0];
        atomicAdd(&g_counts[idx], 1);
    }
}

// ---------------------------------------------------------------------------
__global__ void final_kernel(float* __restrict__ out)
{
    __shared__ float red[1024];
    const int tid = threadIdx.x;

    float s = 0.0f;
    for (int i = 0; i < N_ROWS / 1024; i++) s += g_partial[tid + i * 1024];
    red[tid] = s;
    __syncthreads();
    for (int off = 512; off; off >>= 1) {
        if (tid < off) red[tid] += red[tid + off];
        __syncthreads();
    }
    if (tid == 0) out[0] = 0.25f * red[0] / (float)((size_t)N_ROWS * D_DIM);
    __syncthreads();

    float p = 0.0f;
    for (int i = 0; i < K_CODES / 1024; i++) {
        float c  = (float)g_counts[tid + i * 1024];
        float pr = c * (1.0f / (float)N_ROWS);
        p += pr * logf(pr + 1e-10f);
    }
    red[tid] = p;
    __syncthreads();
    for (int off = 512; off; off >>= 1) {
        if (tid < off) red[tid] += red[tid + off];
        __syncthreads();
    }
    if (tid == 0) out[OFF_PERP] = expf(-red[0]);
}

// ---------------------------------------------------------------------------
extern "C" void kernel_launch(void* const* d_in, const int* in_sizes, int n_in,
                              void* d_out, int out_size)
{
    const float *x0 = nullptr, *x1 = nullptr, *W = nullptr, *b = nullptr, *emb = nullptr;
    for (int i = 0; i < n_in; i++) {
        const float* p = (const float*)d_in[i];
        const long long s = in_sizes[i];
        if (s == (long long)N_ROWS * HALFW)       { if (!x0) x0 = p; else x1 = p; }
        else if (s == (long long)D_DIM * D_DIM)   W = p;
        else if (s == (long long)D_DIM)           b = p;
        else if (s == (long long)K_CODES * D_DIM) emb = p;
    }
    float* out = (float*)d_out;

    static int smem_set = 0;
    if (!smem_set) {
        cudaFuncSetAttribute(gemm1_mma_kernel,
                             cudaFuncAttributeMaxDynamicSharedMemorySize, WRING);
        cudaFuncSetAttribute(gemm2_pass1_kernel,
                             cudaFuncAttributeMaxDynamicSharedMemorySize, WRING);
        cudaFuncSetAttribute(gemm2_pass2_kernel,
                             cudaFuncAttributeMaxDynamicSharedMemorySize, RING_BYTES);
        smem_set = 1;
    }

    prep_x_kernel<<<(N_ROWS * D_DIM) / 1024, 256>>>(x0, x1);
    prep_w_kernel<<<(D_DIM * D_DIM) / 1024, 256>>>(W);
    prep_emb_kernel<<<K_CODES, 128>>>(emb);
    gemm1_mma_kernel<<<dim3(2, N_ROWS / 128), 256, WRING>>>(b);
    gemm2_pass1_kernel<<<N_ROWS / 128, 256, WRING>>>();
    gather_kernel<<<1024, 128>>>();
    gemm2_pass2_kernel<<<(MAXF / 128) * 16, 256, RING_BYTES>>>();
    combine_kernel<<<32, 256>>>();
    fallback_kernel<<<2048, 256>>>(emb);
    epilogue_kernel<<<N_ROWS, 128>>>(emb, out);
    final_kernel<<<1, 1024>>>(out);
}

// round 13
// speedup vs baseline: 1.1436x; 1.1436x over previous
#include <cuda_runtime.h>
#include <cuda_bf16.h>
#include <math.h>
#include <stdint.h>

// Problem constants
#define N_ROWS  32768
#define D_DIM   512
#define K_CODES 2048
#define HALFW   256

// Output layout
#define OFF_QOUT 1
#define OFF_PERP (1 + N_ROWS * D_DIM)
#define OFF_ENC  (2 + N_ROWS * D_DIM)   // 8-byte aligned only

#define MARGIN1 0.25f
#define MARGIN2 0.02f
#define MAXF    8192

// Scratch
__device__ float         g_h[(size_t)N_ROWS * D_DIM];
__device__ __nv_bfloat16 g_hhi[(size_t)N_ROWS * D_DIM];
__device__ __nv_bfloat16 g_hlo[(size_t)N_ROWS * D_DIM];
__device__ __nv_bfloat16 g_ehi[(size_t)K_CODES * D_DIM];
__device__ __nv_bfloat16 g_elo[(size_t)K_CODES * D_DIM];
__device__ __nv_bfloat16 g_x1[(size_t)N_ROWS * D_DIM];
__device__ __nv_bfloat16 g_x2[(size_t)N_ROWS * D_DIM];
__device__ __nv_bfloat16 g_w1[(size_t)D_DIM * D_DIM];
__device__ __nv_bfloat16 g_w2[(size_t)D_DIM * D_DIM];
__device__ __nv_bfloat16 g_fhi[(size_t)MAXF * D_DIM];
__device__ __nv_bfloat16 g_flo[(size_t)MAXF * D_DIM];
__device__ unsigned long long g_p2k[(size_t)MAXF * 16];
__device__ float g_p2v[(size_t)MAXF * 16];
__device__ float g_en[K_CODES];
__device__ int   g_idx[N_ROWS];
__device__ float g_partial[N_ROWS];
__device__ int   g_counts[K_CODES];
__device__ int   g_nflag;
__device__ int   g_flagged[N_ROWS];
__device__ int   g_nflag1;
__device__ int   g_flag1[N_ROWS];
__device__ unsigned long long g_best[N_ROWS];

// ---------------------------------------------------------------------------
// PTX helpers
// ---------------------------------------------------------------------------
__device__ __forceinline__ void mma16816(float* c, const uint32_t* a, const uint32_t* b) {
    asm volatile(
        "mma.sync.aligned.m16n8k16.row.col.f32.bf16.bf16.f32 "
        "{%0,%1,%2,%3}, {%4,%5,%6,%7}, {%8,%9}, {%0,%1,%2,%3};"
        : "+f"(c[0]), "+f"(c[1]), "+f"(c[2]), "+f"(c[3])
        : "r"(a[0]), "r"(a[1]), "r"(a[2]), "r"(a[3]), "r"(b[0]), "r"(b[1]));
}
__device__ __forceinline__ void ldsm_x4(uint32_t* r, uint32_t addr) {
    asm volatile("ldmatrix.sync.aligned.m8n8.x4.shared.b16 {%0,%1,%2,%3}, [%4];"
                 : "=r"(r[0]), "=r"(r[1]), "=r"(r[2]), "=r"(r[3]) : "r"(addr));
}
__device__ __forceinline__ void cp16(uint32_t dst_smem, const void* src) {
    asm volatile("cp.async.cg.shared.global [%0], [%1], 16;" :: "r"(dst_smem), "l"(src));
}
#define CP_COMMIT() asm volatile("cp.async.commit_group;" ::: "memory")
#define CP_WAIT(N)  asm volatile("cp.async.wait_group %0;" :: "n"(N) : "memory")

__device__ __forceinline__ uint32_t fmap(float f) {
    uint32_t u = __float_as_uint(f);
    return (u & 0x80000000u) ? ~u : (u | 0x80000000u);
}
__device__ __forceinline__ float funmap(uint32_t m) {
    return (m & 0x80000000u) ? __uint_as_float(m ^ 0x80000000u) : __uint_as_float(~m);
}

#define SPITCH 72
#define STAGE_BYTES (128 * SPITCH * 2)
#define RING_BYTES  (2 * 2 * STAGE_BYTES)

// ---------------------------------------------------------------------------
// prep_xw: merged x split (blocks 0..16383) + W split (blocks 16384..16639)
// ---------------------------------------------------------------------------
__global__ void prep_xw_kernel(const float* __restrict__ x0, const float* __restrict__ x1,
                               const float* __restrict__ W)
{
    const int blk = blockIdx.x;
    if (blk < (N_ROWS * D_DIM) / 1024) {
        const size_t i = ((size_t)blk * 256 + threadIdx.x) * 4;
        const int col = (int)(i & (D_DIM - 1));
        const size_t row = i >> 9;
        const float* src = (col < HALFW) ? (x0 + row * HALFW + col)
                                         : (x1 + row * HALFW + (col - HALFW));
        float4 v = *(const float4*)src;
        float e[4] = {v.x, v.y, v.z, v.w};
        __nv_bfloat16 a[4], b[4];
#pragma unroll
        for (int j = 0; j < 4; j++) {
            a[j] = __float2bfloat16_rn(e[j]);
            b[j] = __float2bfloat16_rn(e[j] - __bfloat162float(a[j]));
        }
        *(__nv_bfloat162*)(g_x1 + i)     = __nv_bfloat162(a[0], a[1]);
        *(__nv_bfloat162*)(g_x1 + i + 2) = __nv_bfloat162(a[2], a[3]);
        *(__nv_bfloat162*)(g_x2 + i)     = __nv_bfloat162(b[0], b[1]);
        *(__nv_bfloat162*)(g_x2 + i + 2) = __nv_bfloat162(b[2], b[3]);
    } else {
        const size_t i = ((size_t)(blk - (N_ROWS * D_DIM) / 1024) * 256 + threadIdx.x) * 4;
        float4 v = *(const float4*)(W + i);
        float e[4] = {v.x, v.y, v.z, v.w};
        __nv_bfloat16 a[4], b[4];
#pragma unroll
        for (int j = 0; j < 4; j++) {
            a[j] = __float2bfloat16_rn(e[j]);
            b[j] = __float2bfloat16_rn(e[j] - __bfloat162float(a[j]));
        }
        *(__nv_bfloat162*)(g_w1 + i)     = __nv_bfloat162(a[0], a[1]);
        *(__nv_bfloat162*)(g_w1 + i + 2) = __nv_bfloat162(a[2], a[3]);
        *(__nv_bfloat162*)(g_w2 + i)     = __nv_bfloat162(b[0], b[1]);
        *(__nv_bfloat162*)(g_w2 + i + 2) = __nv_bfloat162(b[2], b[3]);
    }
}

__global__ void prep_emb_kernel(const float* __restrict__ emb)
{
    __shared__ float red[128];
    const int k   = blockIdx.x;
    const int tid = threadIdx.x;
    const size_t base = (size_t)k * D_DIM + tid * 4;
    float4 v = *(const float4*)(emb + base);
    red[tid] = v.x * v.x + v.y * v.y + v.z * v.z + v.w * v.w;

    __nv_bfloat16 hx = __float2bfloat16_rn(v.x), hy = __float2bfloat16_rn(v.y);
    __nv_bfloat16 hz = __float2bfloat16_rn(v.z), hw = __float2bfloat16_rn(v.w);
    __nv_bfloat16 lx = __float2bfloat16_rn(v.x - __bfloat162float(hx));
    __nv_bfloat16 ly = __float2bfloat16_rn(v.y - __bfloat162float(hy));
    __nv_bfloat16 lz = __float2bfloat16_rn(v.z - __bfloat162float(hz));
    __nv_bfloat16 lw = __float2bfloat16_rn(v.w - __bfloat162float(hw));
    *(__nv_bfloat162*)(g_ehi + base)     = __nv_bfloat162(hx, hy);
    *(__nv_bfloat162*)(g_ehi + base + 2) = __nv_bfloat162(hz, hw);
    *(__nv_bfloat162*)(g_elo + base)     = __nv_bfloat162(lx, ly);
    *(__nv_bfloat162*)(g_elo + base + 2) = __nv_bfloat162(lz, lw);

    __syncthreads();
    for (int off = 64; off; off >>= 1) {
        if (tid < off) red[tid] += red[tid + off];
        __syncthreads();
    }
    if (tid == 0) {
        g_en[k] = red[0];
        g_counts[k] = 0;
        if (k == 0) { g_nflag = 0; g_nflag1 = 0; }
    }
}

// ---------------------------------------------------------------------------
// GEMM1: 3-phase (X1W1, X1W2, X2W1), 2-stage single-sync cp.async ring (R9)
// ---------------------------------------------------------------------------
#define NSTEP1 24

__global__ __launch_bounds__(256, 2)
void gemm1_mma_kernel(const float* __restrict__ bias)
{
    extern __shared__ __align__(16) char dsm[];
    const uint32_t smem_u32 = (uint32_t)__cvta_generic_to_shared(dsm);

    const int tid  = threadIdx.x;
    const int lane = tid & 31;
    const int w    = tid >> 5;
    const int wm   = w >> 2;
    const int wn   = w & 3;
    const int lq   = lane >> 2;
    const int lr   = lane & 3;
    const int m0   = blockIdx.y * 128;
    const int n0   = blockIdx.x * 128;

    const int lrow0 = tid >> 3;
    const int lch   = tid & 7;

    const int arow  = (lane < 16) ? lane : (lane - 16);
    const int acol8 = (lane < 16) ? 0 : 8;
    uint32_t aoff[4];
#pragma unroll
    for (int mt = 0; mt < 4; mt++)
        aoff[mt] = (uint32_t)(((wm * 64 + mt * 16 + arow) * SPITCH + acol8) * 2);
    const int bg = lane >> 3;
    uint32_t boff[2];
#pragma unroll
    for (int p = 0; p < 2; p++) {
        int nrow = wn * 32 + (2 * p + (bg >> 1)) * 8 + (lane & 7);
        boff[p] = (uint32_t)((nrow * SPITCH + (bg & 1) * 8) * 2);
    }

    auto load_step = [&](int step, int stage) {
        const int phase = step >> 3;
        const int kk    = (step & 7) * 64;
        const __nv_bfloat16* Ag = (phase < 2) ? g_x1 : g_x2;
        const __nv_bfloat16* Bg = (phase == 1) ? g_w2 : g_w1;
        uint32_t sAb = smem_u32 + stage * 2 * STAGE_BYTES;
        uint32_t sBb = sAb + STAGE_BYTES;
#pragma unroll
        for (int i = 0; i < 4; i++) {
            int r = lrow0 + i * 32;
            cp16(sAb + (uint32_t)((r * SPITCH + lch * 8) * 2),
                 Ag + (size_t)(m0 + r) * D_DIM + kk + lch * 8);
            cp16(sBb + (uint32_t)((r * SPITCH + lch * 8) * 2),
                 Bg + (size_t)(n0 + r) * D_DIM + kk + lch * 8);
        }
    };

    float acc[4][4][4];
#pragma unroll
    for (int a = 0; a < 4; a++)
#pragma unroll
        for (int b = 0; b < 4; b++)
#pragma unroll
            for (int c = 0; c < 4; c++) acc[a][b][c] = 0.0f;

    load_step(0, 0);
    CP_COMMIT();

    for (int cur = 0; cur < NSTEP1; cur++) {
        CP_WAIT(0);
        __syncthreads();
        if (cur + 1 < NSTEP1) {
            load_step(cur + 1, (cur + 1) & 1);
            CP_COMMIT();
        }
        const uint32_t sAu = smem_u32 + (uint32_t)((cur & 1) * 2 * STAGE_BYTES);
        const uint32_t sBu = sAu + STAGE_BYTES;
#pragma unroll
        for (int ks = 0; ks < 4; ks++) {
            uint32_t bfr[4][2];
            {
                uint32_t t0[4], t1[4];
                ldsm_x4(t0, sBu + boff[0] + ks * 32);
                ldsm_x4(t1, sBu + boff[1] + ks * 32);
                bfr[0][0] = t0[0]; bfr[0][1] = t0[1];
                bfr[1][0] = t0[2]; bfr[1][1] = t0[3];
                bfr[2][0] = t1[0]; bfr[2][1] = t1[1];
                bfr[3][0] = t1[2]; bfr[3][1] = t1[3];
            }
#pragma unroll
            for (int mt = 0; mt < 4; mt++) {
                uint32_t afr[4];
                ldsm_x4(afr, sAu + aoff[mt] + ks * 32);
#pragma unroll
                for (int nn = 0; nn < 4; nn++)
                    mma16816(acc[mt][nn], afr, bfr[nn]);
            }
        }
    }

    float bia[4][2];
#pragma unroll
    for (int nn = 0; nn < 4; nn++) {
        int col = n0 + wn * 32 + nn * 8 + lr * 2;
        bia[nn][0] = bias[col];
        bia[nn][1] = bias[col + 1];
    }
#pragma unroll
    for (int mt = 0; mt < 4; mt++) {
#pragma unroll
        for (int half = 0; half < 2; half++) {
            const int row = m0 + wm * 64 + mt * 16 + half * 8 + lq;
#pragma unroll
            for (int nn = 0; nn < 4; nn++) {
                const int col = n0 + wn * 32 + nn * 8 + lr * 2;
                float h0 = acc[mt][nn][half * 2 + 0] + bia[nn][0];
                float h1 = acc[mt][nn][half * 2 + 1] + bia[nn][1];
                const size_t o = (size_t)row * D_DIM + col;
                *(float2*)(g_h + o) = make_float2(h0, h1);
                __nv_bfloat16 p0 = __float2bfloat16_rn(h0);
                __nv_bfloat16 p1 = __float2bfloat16_rn(h1);
                __nv_bfloat16 q0 = __float2bfloat16_rn(h0 - __bfloat162float(p0));
                __nv_bfloat16 q1 = __float2bfloat16_rn(h1 - __bfloat162float(p1));
                *(__nv_bfloat162*)(g_hhi + o) = __nv_bfloat162(p0, p1);
                *(__nv_bfloat162*)(g_hlo + o) = __nv_bfloat162(q0, q1);
            }
        }
    }
}

// ---------------------------------------------------------------------------
// GEMM2 pass 1: single-phase bf16, K=512, top-2 + MARGIN1 flag (R9 shape)
// ---------------------------------------------------------------------------
#define NSTEP_P1 128

__global__ __launch_bounds__(256, 2)
void gemm2_pass1_kernel()
{
    extern __shared__ __align__(16) char dsm[];
    const uint32_t smem_u32 = (uint32_t)__cvta_generic_to_shared(dsm);

    const int tid  = threadIdx.x;
    const int lane = tid & 31;
    const int w    = tid >> 5;
    const int wm   = w >> 2;
    const int wn   = w & 3;
    const int lq   = lane >> 2;
    const int lr   = lane & 3;
    const int m0   = blockIdx.x * 128;

    const int lrow0 = tid >> 3;
    const int lch   = tid & 7;

    const int arow  = (lane < 16) ? lane : (lane - 16);
    const int acol8 = (lane < 16) ? 0 : 8;
    uint32_t aoff[4];
#pragma unroll
    for (int mt = 0; mt < 4; mt++)
        aoff[mt] = (uint32_t)(((wm * 64 + mt * 16 + arow) * SPITCH + acol8) * 2);
    const int bg = lane >> 3;
    uint32_t boff[2];
#pragma unroll
    for (int p = 0; p < 2; p++) {
        int nrow = wn * 32 + (2 * p + (bg >> 1)) * 8 + (lane & 7);
        boff[p] = (uint32_t)((nrow * SPITCH + (bg & 1) * 8) * 2);
    }

    float v1[8], v2[8]; int i1[8];
#pragma unroll
    for (int s = 0; s < 8; s++) { v1[s] = 3.4e38f; v2[s] = 3.4e38f; i1[s] = 0; }

#define UPD(sl, cc, ss) do { float _s = (ss); \
    if (_s < v1[sl]) { v2[sl] = v1[sl]; v1[sl] = _s; i1[sl] = (cc); } \
    else if (_s < v2[sl]) v2[sl] = _s; } while (0)

    auto load_step = [&](int step, int stage) {
        const int nt = step >> 3;
        const int kk = (step & 7) * 64;
        const int n0 = nt * 128;
        uint32_t sAb = smem_u32 + stage * 2 * STAGE_BYTES;
        uint32_t sBb = sAb + STAGE_BYTES;
#pragma unroll
        for (int i = 0; i < 4; i++) {
            int r = lrow0 + i * 32;
            cp16(sAb + (uint32_t)((r * SPITCH + lch * 8) * 2),
                 g_hhi + (size_t)(m0 + r) * D_DIM + kk + lch * 8);
            cp16(sBb + (uint32_t)((r * SPITCH + lch * 8) * 2),
                 g_ehi + (size_t)(n0 + r) * D_DIM + kk + lch * 8);
        }
    };

    load_step(0, 0);
    CP_COMMIT();

    float acc[4][4][4];
    for (int nt = 0; nt < 16; nt++) {
        const int n0 = nt * 128;
#pragma unroll
        for (int a = 0; a < 4; a++)
#pragma unroll
            for (int b = 0; b < 4; b++)
#pragma unroll
                for (int c = 0; c < 4; c++) acc[a][b][c] = 0.0f;

        for (int vc = 0; vc < 8; vc++) {
            const int cur = nt * 8 + vc;
            CP_WAIT(0);
            __syncthreads();
            if (cur + 1 < NSTEP_P1) {
                load_step(cur + 1, (cur + 1) & 1);
                CP_COMMIT();
            }
            const uint32_t sAu = smem_u32 + (uint32_t)((cur & 1) * 2 * STAGE_BYTES);
            const uint32_t sBu = sAu + STAGE_BYTES;
#pragma unroll
            for (int ks = 0; ks < 4; ks++) {
                uint32_t bfr[4][2];
                {
                    uint32_t t0[4], t1[4];
                    ldsm_x4(t0, sBu + boff[0] + ks * 32);
                    ldsm_x4(t1, sBu + boff[1] + ks * 32);
                    bfr[0][0] = t0[0]; bfr[0][1] = t0[1];
                    bfr[1][0] = t0[2]; bfr[1][1] = t0[3];
                    bfr[2][0] = t1[0]; bfr[2][1] = t1[1];
                    bfr[3][0] = t1[2]; bfr[3][1] = t1[3];
                }
#pragma unroll
                for (int mt = 0; mt < 4; mt++) {
                    uint32_t afr[4];
                    ldsm_x4(afr, sAu + aoff[mt] + ks * 32);
#pragma unroll
                    for (int nn = 0; nn < 4; nn++)
                        mma16816(acc[mt][nn], afr, bfr[nn]);
                }
            }
        }

#pragma unroll
        for (int mt = 0; mt < 4; mt++) {
#pragma unroll
            for (int nn = 0; nn < 4; nn++) {
                const int col = n0 + wn * 32 + nn * 8 + lr * 2;
                const float e0 = g_en[col], e1 = g_en[col + 1];
                const int s0 = mt * 2, s1 = mt * 2 + 1;
                UPD(s0, col,     e0 - 2.0f * acc[mt][nn][0]);
                UPD(s0, col + 1, e1 - 2.0f * acc[mt][nn][1]);
                UPD(s1, col,     e0 - 2.0f * acc[mt][nn][2]);
                UPD(s1, col + 1, e1 - 2.0f * acc[mt][nn][3]);
            }
        }
    }

#pragma unroll
    for (int off = 1; off <= 2; off <<= 1) {
#pragma unroll
        for (int sl = 0; sl < 8; sl++) {
            float ov1 = __shfl_xor_sync(0xffffffffu, v1[sl], off);
            int   oi1 = __shfl_xor_sync(0xffffffffu, i1[sl], off);
            float ov2 = __shfl_xor_sync(0xffffffffu, v2[sl], off);
            if (ov1 < v1[sl] || (ov1 == v1[sl] && oi1 < i1[sl])) {
                v2[sl] = fminf(v1[sl], ov2); v1[sl] = ov1; i1[sl] = oi1;
            } else {
                v2[sl] = fminf(v2[sl], ov1);
            }
        }
    }

    __syncthreads();
    float* rv1 = (float*)dsm;
    int*   ri1 = (int*)(dsm + 2048);
    float* rv2 = (float*)(dsm + 4096);
    if (lr == 0) {
#pragma unroll
        for (int sl = 0; sl < 8; sl++) {
            int row = wm * 64 + (sl >> 1) * 16 + (sl & 1) * 8 + lq;
            rv1[row * 4 + wn] = v1[sl];
            ri1[row * 4 + wn] = i1[sl];
            rv2[row * 4 + wn] = v2[sl];
        }
    }
    __syncthreads();
    if (tid < 128) {
        float bv1 = rv1[tid * 4]; int bi1 = ri1[tid * 4]; float bv2 = rv2[tid * 4];
#pragma unroll
        for (int j = 1; j < 4; j++) {
            float ov1 = rv1[tid * 4 + j]; int oi1 = ri1[tid * 4 + j]; float ov2 = rv2[tid * 4 + j];
            if (ov1 < bv1 || (ov1 == bv1 && oi1 < bi1)) {
                bv2 = fminf(bv1, ov2); bv1 = ov1; bi1 = oi1;
            } else {
                bv2 = fminf(bv2, ov1);
            }
        }
        const int row = m0 + tid;
        g_idx[row] = bi1;
        if (bv2 - bv1 <= MARGIN1) {
            int slot = atomicAdd(&g_nflag1, 1);
            if (slot < MAXF) g_flag1[slot] = row;
        }
    }
}

// ---------------------------------------------------------------------------
// gather flagged rows
// ---------------------------------------------------------------------------
__global__ __launch_bounds__(128)
void gather_kernel()
{
    const int cnt = min(g_nflag1, MAXF);
    const int tid = threadIdx.x;
    for (int f = blockIdx.x; f < cnt; f += gridDim.x) {
        const int row = g_flag1[f];
        const uint32_t* shi = (const uint32_t*)(g_hhi + (size_t)row * D_DIM);
        const uint32_t* slo = (const uint32_t*)(g_hlo + (size_t)row * D_DIM);
        uint32_t* dhi = (uint32_t*)(g_fhi + (size_t)f * D_DIM);
        uint32_t* dlo = (uint32_t*)(g_flo + (size_t)f * D_DIM);
        dhi[tid * 2] = shi[tid * 2]; dhi[tid * 2 + 1] = shi[tid * 2 + 1];
        dlo[tid * 2] = slo[tid * 2]; dlo[tid * 2 + 1] = slo[tid * 2 + 1];
    }
}

// ---------------------------------------------------------------------------
// pass 2: 3-phase split for flagged rows (R9 shape)
// ---------------------------------------------------------------------------
__global__ __launch_bounds__(256, 2)
void gemm2_pass2_kernel()
{
    const int cnt = min(g_nflag1, MAXF);
    const int rt = blockIdx.x >> 4;
    const int nt = blockIdx.x & 15;
    if (rt * 128 >= cnt) return;

    extern __shared__ __align__(16) char dsm[];
    const uint32_t smem_u32 = (uint32_t)__cvta_generic_to_shared(dsm);

    const int tid  = threadIdx.x;
    const int lane = tid & 31;
    const int w    = tid >> 5;
    const int wm   = w >> 2;
    const int wn   = w & 3;
    const int lq   = lane >> 2;
    const int lr   = lane & 3;
    const int f0   = rt * 128;
    const int n0   = nt * 128;

    const int lrow0 = tid >> 3;
    const int lch   = tid & 7;

    const int arow  = (lane < 16) ? lane : (lane - 16);
    const int acol8 = (lane < 16) ? 0 : 8;
    uint32_t aoff[4];
#pragma unroll
    for (int mt = 0; mt < 4; mt++)
        aoff[mt] = (uint32_t)(((wm * 64 + mt * 16 + arow) * SPITCH + acol8) * 2);
    const int bg = lane >> 3;
    uint32_t boff[2];
#pragma unroll
    for (int p = 0; p < 2; p++) {
        int nrow = wn * 32 + (2 * p + (bg >> 1)) * 8 + (lane & 7);
        boff[p] = (uint32_t)((nrow * SPITCH + (bg & 1) * 8) * 2);
    }

    auto load_step = [&](int step, int stage) {
        const int phase = step >> 3;
        const int kk    = (step & 7) * 64;
        const __nv_bfloat16* Ag = (phase < 2)  ? g_fhi : g_flo;
        const __nv_bfloat16* Bg = (phase == 1) ? g_elo : g_ehi;
        uint32_t sAb = smem_u32 + stage * 2 * STAGE_BYTES;
        uint32_t sBb = sAb + STAGE_BYTES;
#pragma unroll
        for (int i = 0; i < 4; i++) {
            int r = lrow0 + i * 32;
            cp16(sAb + (uint32_t)((r * SPITCH + lch * 8) * 2),
                 Ag + (size_t)(f0 + r) * D_DIM + kk + lch * 8);
            cp16(sBb + (uint32_t)((r * SPITCH + lch * 8) * 2),
                 Bg + (size_t)(n0 + r) * D_DIM + kk + lch * 8);
        }
    };

    float acc[4][4][4];
#pragma unroll
    for (int a = 0; a < 4; a++)
#pragma unroll
        for (int b = 0; b < 4; b++)
#pragma unroll
            for (int c = 0; c < 4; c++) acc[a][b][c] = 0.0f;

    load_step(0, 0);
    CP_COMMIT();

    for (int cur = 0; cur < 24; cur++) {
        CP_WAIT(0);
        __syncthreads();
        if (cur + 1 < 24) {
            load_step(cur + 1, (cur + 1) & 1);
            CP_COMMIT();
        }
        const uint32_t sAu = smem_u32 + (uint32_t)((cur & 1) * 2 * STAGE_BYTES);
        const uint32_t sBu = sAu + STAGE_BYTES;
#pragma unroll
        for (int ks = 0; ks < 4; ks++) {
            uint32_t bfr[4][2];
            {
                uint32_t t0[4], t1[4];
                ldsm_x4(t0, sBu + boff[0] + ks * 32);
                ldsm_x4(t1, sBu + boff[1] + ks * 32);
                bfr[0][0] = t0[0]; bfr[0][1] = t0[1];
                bfr[1][0] = t0[2]; bfr[1][1] = t0[3];
                bfr[2][0] = t1[0]; bfr[2][1] = t1[1];
                bfr[3][0] = t1[2]; bfr[3][1] = t1[3];
            }
#pragma unroll
            for (int mt = 0; mt < 4; mt++) {
                uint32_t afr[4];
                ldsm_x4(afr, sAu + aoff[mt] + ks * 32);
#pragma unroll
                for (int nn = 0; nn < 4; nn++)
                    mma16816(acc[mt][nn], afr, bfr[nn]);
            }
        }
    }

    float v1[8], v2[8]; int i1[8];
#pragma unroll
    for (int s = 0; s < 8; s++) { v1[s] = 3.4e38f; v2[s] = 3.4e38f; i1[s] = 0; }
#pragma unroll
    for (int mt = 0; mt < 4; mt++) {
#pragma unroll
        for (int nn = 0; nn < 4; nn++) {
            const int col = n0 + wn * 32 + nn * 8 + lr * 2;
            const float e0 = g_en[col], e1 = g_en[col + 1];
            const int s0 = mt * 2, s1 = mt * 2 + 1;
            UPD(s0, col,     e0 - 2.0f * acc[mt][nn][0]);
            UPD(s0, col + 1, e1 - 2.0f * acc[mt][nn][1]);
            UPD(s1, col,     e0 - 2.0f * acc[mt][nn][2]);
            UPD(s1, col + 1, e1 - 2.0f * acc[mt][nn][3]);
        }
    }

#pragma unroll
    for (int off = 1; off <= 2; off <<= 1) {
#pragma unroll
        for (int sl = 0; sl < 8; sl++) {
            float ov1 = __shfl_xor_sync(0xffffffffu, v1[sl], off);
            int   oi1 = __shfl_xor_sync(0xffffffffu, i1[sl], off);
            float ov2 = __shfl_xor_sync(0xffffffffu, v2[sl], off);
            if (ov1 < v1[sl] || (ov1 == v1[sl] && oi1 < i1[sl])) {
                v2[sl] = fminf(v1[sl], ov2); v1[sl] = ov1; i1[sl] = oi1;
            } else {
                v2[sl] = fminf(v2[sl], ov1);
            }
        }
    }

    __syncthreads();
    float* rv1 = (float*)dsm;
    int*   ri1 = (int*)(dsm + 2048);
    float* rv2 = (float*)(dsm + 4096);
    if (lr == 0) {
#pragma unroll
        for (int sl = 0; sl < 8; sl++) {
            int row = wm * 64 + (sl >> 1) * 16 + (sl & 1) * 8 + lq;
            rv1[row * 4 + wn] = v1[sl];
            ri1[row * 4 + wn] = i1[sl];
            rv2[row * 4 + wn] = v2[sl];
        }
    }
    __syncthreads();
    if (tid < 128) {
        float bv1 = rv1[tid * 4]; int bi1 = ri1[tid * 4]; float bv2 = rv2[tid * 4];
#pragma unroll
        for (int j = 1; j < 4; j++) {
            float ov1 = rv1[tid * 4 + j]; int oi1 = ri1[tid * 4 + j]; float ov2 = rv2[tid * 4 + j];
            if (ov1 < bv1 || (ov1 == bv1 && oi1 < bi1)) {
                bv2 = fminf(bv1, ov2); bv1 = ov1; bi1 = oi1;
            } else {
                bv2 = fminf(bv2, ov1);
            }
        }
        const int crow = f0 + tid;
        g_p2k[(size_t)crow * 16 + nt] =
            ((unsigned long long)fmap(bv1) << 32) | (unsigned)bi1;
        g_p2v[(size_t)crow * 16 + nt] = bv2;
    }
}

// ---------------------------------------------------------------------------
// combine
// ---------------------------------------------------------------------------
__global__ __launch_bounds__(256)
void combine_kernel()
{
    const int cnt = min(g_nflag1, MAXF);
    for (int f = blockIdx.x * 256 + threadIdx.x; f < cnt; f += gridDim.x * 256) {
        unsigned long long bestk = 0xFFFFFFFFFFFFFFFFull;
#pragma unroll
        for (int j = 0; j < 16; j++)
            bestk = min(bestk, g_p2k[(size_t)f * 16 + j]);
        float s1 = funmap((uint32_t)(bestk >> 32));
        float s2 = 3.4e38f;
#pragma unroll
        for (int j = 0; j < 16; j++) {
            unsigned long long k = g_p2k[(size_t)f * 16 + j];
            float v2 = g_p2v[(size_t)f * 16 + j];
            if (k != bestk) s2 = fminf(s2, funmap((uint32_t)(k >> 32)));
            s2 = fminf(s2, v2);
        }
        const int orig = g_flag1[f];
        if (s2 - s1 <= MARGIN2) {
            g_idx[orig]  = -1;
            g_best[orig] = 0xFFFFFFFFFFFFFFFFull;
            int slot = atomicAdd(&g_nflag, 1);
            g_flagged[slot] = orig;
        } else {
            g_idx[orig] = (int)(bestk & 0xFFFFFFFFull);
        }
    }
}

// ---------------------------------------------------------------------------
// Exact fp32 fallback
// ---------------------------------------------------------------------------
__global__ __launch_bounds__(256)
void fallback_kernel(const float* __restrict__ emb)
{
    __shared__ float hrow[D_DIM];
    const int tid = threadIdx.x;
    const int cnt = g_nflag;
    const int total = cnt * 8;

    for (int wk = blockIdx.x; wk < total; wk += gridDim.x) {
        const int f     = wk >> 3;
        const int chunk = wk & 7;
        const int row   = g_flagged[f];

        if (tid < 128)
            *(float4*)(hrow + tid * 4) = *(const float4*)(g_h + (size_t)row * D_DIM + tid * 4);
        __syncthreads();

        const int k = chunk * 256 + tid;
        const float4* ep = (const float4*)(emb + (size_t)k * D_DIM);
        float a0 = 0.f, a1 = 0.f, a2 = 0.f, a3 = 0.f;
#pragma unroll 16
        for (int d4 = 0; d4 < D_DIM / 4; d4++) {
            float4 e = ep[d4];
            float4 h = *(const float4*)(hrow + d4 * 4);
            a0 += e.x * h.x; a1 += e.y * h.y; a2 += e.z * h.z; a3 += e.w * h.w;
        }
        float s = g_en[k] - 2.0f * ((a0 + a1) + (a2 + a3));
        unsigned long long key = ((unsigned long long)fmap(s) << 32) | (unsigned)k;
        atomicMin(&g_best[row], key);
        __syncthreads();
    }
}

// ---------------------------------------------------------------------------
// Epilogue
// ---------------------------------------------------------------------------
__global__ void epilogue_kernel(const float* __restrict__ emb, float* __restrict__ out)
{
    __shared__ float red[128];
    const int n   = blockIdx.x;
    const int tid = threadIdx.x;
    int idx = g_idx[n];
    if (idx < 0) idx = (int)(g_best[n] & 0xFFFFFFFFull);

    float4 hv = *(const float4*)(g_h + (size_t)n * D_DIM + tid * 4);
    float4 qv = *(const float4*)(emb + (size_t)idx * D_DIM + tid * 4);
    float d0 = qv.x - hv.x, d1 = qv.y - hv.y, d2 = qv.z - hv.z, d3 = qv.w - hv.w;

    float* qo = out + OFF_QOUT + (size_t)n * D_DIM + tid * 4;
    __stcs(qo + 0, hv.x + d0);
    __stcs(qo + 1, hv.y + d1);
    __stcs(qo + 2, hv.z + d2);
    __stcs(qo + 3, hv.w + d3);

    red[tid] = d0 * d0 + d1 * d1 + d2 * d2 + d3 * d3;

    float2* er2 = (float2*)(out + OFF_ENC + (size_t)n * K_CODES);
    const int unit = idx >> 1, comp = idx & 1;
#pragma unroll
    for (int i = 0; i < 8; i++) {
        int u = tid + i * 128;
        float2 v = make_float2(0.0f, 0.0f);
        if (u == unit) { if (comp == 0) v.x = 1.0f; else v.y = 1.0f; }
        __stcs(er2 + u, v);
    }

    __syncthreads();
    for (int off = 64; off; off >>= 1) {
        if (tid < off) red[tid] += red[tid + off];
        __syncthreads();
    }
    if (tid == 0) {
        g_partial[n] = red[0];
        atomicAdd(&g_counts[idx], 1);
    }
}

// ---------------------------------------------------------------------------
__global__ void final_kernel(float* __restrict__ out)
{
    __shared__ float red[1024];
    const int tid = threadIdx.x;

    float s = 0.0f;
    for (int i = 0; i < N_ROWS / 1024; i++) s += g_partial[tid + i * 1024];
    red[tid] = s;
    __syncthreads();
    for (int off = 512; off; off >>= 1) {
        if (tid < off) red[tid] += red[tid + off];
        __syncthreads();
    }
    if (tid == 0) out[0] = 0.25f * red[0] / (float)((size_t)N_ROWS * D_DIM);
    __syncthreads();

    float p = 0.0f;
    for (int i = 0; i < K_CODES / 1024; i++) {
        float c  = (float)g_counts[tid + i * 1024];
        float pr = c * (1.0f / (float)N_ROWS);
        p += pr * logf(pr + 1e-10f);
    }
    red[tid] = p;
    __syncthreads();
    for (int off = 512; off; off >>= 1) {
        if (tid < off) red[tid] += red[tid + off];
        __syncthreads();
    }
    if (tid == 0) out[OFF_PERP] = expf(-red[0]);
}

// ---------------------------------------------------------------------------
extern "C" void kernel_launch(void* const* d_in, const int* in_sizes, int n_in,
                              void* d_out, int out_size)
{
    const float *x0 = nullptr, *x1 = nullptr, *W = nullptr, *b = nullptr, *emb = nullptr;
    for (int i = 0; i < n_in; i++) {
        const float* p = (const float*)d_in[i];
        const long long s = in_sizes[i];
        if (s == (long long)N_ROWS * HALFW)       { if (!x0) x0 = p; else x1 = p; }
        else if (s == (long long)D_DIM * D_DIM)   W = p;
        else if (s == (long long)D_DIM)           b = p;
        else if (s == (long long)K_CODES * D_DIM) emb = p;
    }
    float* out = (float*)d_out;

    static int smem_set = 0;
    if (!smem_set) {
        cudaFuncSetAttribute(gemm1_mma_kernel,
                             cudaFuncAttributeMaxDynamicSharedMemorySize, RING_BYTES);
        cudaFuncSetAttribute(gemm2_pass1_kernel,
                             cudaFuncAttributeMaxDynamicSharedMemorySize, RING_BYTES);
        cudaFuncSetAttribute(gemm2_pass2_kernel,
                             cudaFuncAttributeMaxDynamicSharedMemorySize, RING_BYTES);
        smem_set = 1;
    }

    prep_xw_kernel<<<(N_ROWS * D_DIM) / 1024 + (D_DIM * D_DIM) / 1024, 256>>>(x0, x1, W);
    prep_emb_kernel<<<K_CODES, 128>>>(emb);
    gemm1_mma_kernel<<<dim3(D_DIM / 128, N_ROWS / 128), 256, RING_BYTES>>>(b);
    gemm2_pass1_kernel<<<N_ROWS / 128, 256, RING_BYTES>>>();
    gather_kernel<<<1024, 128>>>();
    gemm2_pass2_kernel<<<(MAXF / 128) * 16, 256, RING_BYTES>>>();
    combine_kernel<<<32, 256>>>();
    fallback_kernel<<<2048, 256>>>(emb);
    epilogue_kernel<<<N_ROWS, 128>>>(emb, out);
    final_kernel<<<1, 1024>>>(out);
}

// round 14
// speedup vs baseline: 1.1473x; 1.0033x over previous
#include <cuda_runtime.h>
#include <cuda_bf16.h>
#include <math.h>
#include <stdint.h>

// Problem constants
#define N_ROWS  32768
#define D_DIM   512
#define K_CODES 2048
#define HALFW   256

// Output layout
#define OFF_QOUT 1
#define OFF_PERP (1 + N_ROWS * D_DIM)
#define OFF_ENC  (2 + N_ROWS * D_DIM)   // 8-byte aligned only

#define MARGIN1 0.25f
#define MARGIN2 0.02f
#define MAXF    8192

// Scratch
__device__ float         g_h[(size_t)N_ROWS * D_DIM];
__device__ __nv_bfloat16 g_hhi[(size_t)N_ROWS * D_DIM];
__device__ __nv_bfloat16 g_hlo[(size_t)N_ROWS * D_DIM];
__device__ __nv_bfloat16 g_ehi[(size_t)K_CODES * D_DIM];
__device__ __nv_bfloat16 g_elo[(size_t)K_CODES * D_DIM];
__device__ __nv_bfloat16 g_x1[(size_t)N_ROWS * D_DIM];
__device__ __nv_bfloat16 g_x2[(size_t)N_ROWS * D_DIM];
__device__ __nv_bfloat16 g_w1[(size_t)D_DIM * D_DIM];
__device__ __nv_bfloat16 g_w2[(size_t)D_DIM * D_DIM];
__device__ __nv_bfloat16 g_fhi[(size_t)MAXF * D_DIM];
__device__ __nv_bfloat16 g_flo[(size_t)MAXF * D_DIM];
__device__ unsigned long long g_p2k[(size_t)MAXF * 16];
__device__ float g_p2v[(size_t)MAXF * 16];
__device__ float g_en[K_CODES];
__device__ int   g_idx[N_ROWS];
__device__ float g_partial[N_ROWS];
__device__ int   g_counts[K_CODES];
__device__ int   g_nflag;
__device__ int   g_flagged[N_ROWS];
__device__ int   g_nflag1;
__device__ int   g_flag1[N_ROWS];
__device__ unsigned long long g_best[N_ROWS];

// ---------------------------------------------------------------------------
// PTX helpers
// ---------------------------------------------------------------------------
__device__ __forceinline__ void mma16816(float* c, const uint32_t* a, const uint32_t* b) {
    asm volatile(
        "mma.sync.aligned.m16n8k16.row.col.f32.bf16.bf16.f32 "
        "{%0,%1,%2,%3}, {%4,%5,%6,%7}, {%8,%9}, {%0,%1,%2,%3};"
        : "+f"(c[0]), "+f"(c[1]), "+f"(c[2]), "+f"(c[3])
        : "r"(a[0]), "r"(a[1]), "r"(a[2]), "r"(a[3]), "r"(b[0]), "r"(b[1]));
}
__device__ __forceinline__ void ldsm_x4(uint32_t* r, uint32_t addr) {
    asm volatile("ldmatrix.sync.aligned.m8n8.x4.shared.b16 {%0,%1,%2,%3}, [%4];"
                 : "=r"(r[0]), "=r"(r[1]), "=r"(r[2]), "=r"(r[3]) : "r"(addr));
}
__device__ __forceinline__ void cp16(uint32_t dst_smem, const void* src) {
    asm volatile("cp.async.cg.shared.global [%0], [%1], 16;" :: "r"(dst_smem), "l"(src));
}
#define CP_COMMIT() asm volatile("cp.async.commit_group;" ::: "memory")
#define CP_WAIT(N)  asm volatile("cp.async.wait_group %0;" :: "n"(N) : "memory")

__device__ __forceinline__ uint32_t fmap(float f) {
    uint32_t u = __float_as_uint(f);
    return (u & 0x80000000u) ? ~u : (u | 0x80000000u);
}
__device__ __forceinline__ float funmap(uint32_t m) {
    return (m & 0x80000000u) ? __uint_as_float(m ^ 0x80000000u) : __uint_as_float(~m);
}

#define SPITCH 72
#define STAGE_BYTES (128 * SPITCH * 2)
#define RING_BYTES  (2 * 2 * STAGE_BYTES)

// ---------------------------------------------------------------------------
// prep_xw: merged x split (blocks 0..16383) + W split (blocks 16384..16639)
// ---------------------------------------------------------------------------
__global__ void prep_xw_kernel(const float* __restrict__ x0, const float* __restrict__ x1,
                               const float* __restrict__ W)
{
    const int blk = blockIdx.x;
    if (blk < (N_ROWS * D_DIM) / 1024) {
        const size_t i = ((size_t)blk * 256 + threadIdx.x) * 4;
        const int col = (int)(i & (D_DIM - 1));
        const size_t row = i >> 9;
        const float* src = (col < HALFW) ? (x0 + row * HALFW + col)
                                         : (x1 + row * HALFW + (col - HALFW));
        float4 v = *(const float4*)src;
        float e[4] = {v.x, v.y, v.z, v.w};
        __nv_bfloat16 a[4], b[4];
#pragma unroll
        for (int j = 0; j < 4; j++) {
            a[j] = __float2bfloat16_rn(e[j]);
            b[j] = __float2bfloat16_rn(e[j] - __bfloat162float(a[j]));
        }
        *(__nv_bfloat162*)(g_x1 + i)     = __nv_bfloat162(a[0], a[1]);
        *(__nv_bfloat162*)(g_x1 + i + 2) = __nv_bfloat162(a[2], a[3]);
        *(__nv_bfloat162*)(g_x2 + i)     = __nv_bfloat162(b[0], b[1]);
        *(__nv_bfloat162*)(g_x2 + i + 2) = __nv_bfloat162(b[2], b[3]);
    } else {
        const size_t i = ((size_t)(blk - (N_ROWS * D_DIM) / 1024) * 256 + threadIdx.x) * 4;
        float4 v = *(const float4*)(W + i);
        float e[4] = {v.x, v.y, v.z, v.w};
        __nv_bfloat16 a[4], b[4];
#pragma unroll
        for (int j = 0; j < 4; j++) {
            a[j] = __float2bfloat16_rn(e[j]);
            b[j] = __float2bfloat16_rn(e[j] - __bfloat162float(a[j]));
        }
        *(__nv_bfloat162*)(g_w1 + i)     = __nv_bfloat162(a[0], a[1]);
        *(__nv_bfloat162*)(g_w1 + i + 2) = __nv_bfloat162(a[2], a[3]);
        *(__nv_bfloat162*)(g_w2 + i)     = __nv_bfloat162(b[0], b[1]);
        *(__nv_bfloat162*)(g_w2 + i + 2) = __nv_bfloat162(b[2], b[3]);
    }
}

__global__ void prep_emb_kernel(const float* __restrict__ emb)
{
    __shared__ float red[128];
    const int k   = blockIdx.x;
    const int tid = threadIdx.x;
    const size_t base = (size_t)k * D_DIM + tid * 4;
    float4 v = *(const float4*)(emb + base);
    red[tid] = v.x * v.x + v.y * v.y + v.z * v.z + v.w * v.w;

    __nv_bfloat16 hx = __float2bfloat16_rn(v.x), hy = __float2bfloat16_rn(v.y);
    __nv_bfloat16 hz = __float2bfloat16_rn(v.z), hw = __float2bfloat16_rn(v.w);
    __nv_bfloat16 lx = __float2bfloat16_rn(v.x - __bfloat162float(hx));
    __nv_bfloat16 ly = __float2bfloat16_rn(v.y - __bfloat162float(hy));
    __nv_bfloat16 lz = __float2bfloat16_rn(v.z - __bfloat162float(hz));
    __nv_bfloat16 lw = __float2bfloat16_rn(v.w - __bfloat162float(hw));
    *(__nv_bfloat162*)(g_ehi + base)     = __nv_bfloat162(hx, hy);
    *(__nv_bfloat162*)(g_ehi + base + 2) = __nv_bfloat162(hz, hw);
    *(__nv_bfloat162*)(g_elo + base)     = __nv_bfloat162(lx, ly);
    *(__nv_bfloat162*)(g_elo + base + 2) = __nv_bfloat162(lz, lw);

    __syncthreads();
    for (int off = 64; off; off >>= 1) {
        if (tid < off) red[tid] += red[tid + off];
        __syncthreads();
    }
    if (tid == 0) {
        g_en[k] = red[0];
        g_counts[k] = 0;
        if (k == 0) { g_nflag = 0; g_nflag1 = 0; }
    }
}

// ---------------------------------------------------------------------------
// GEMM1: 3-phase (X1W1, X1W2, X2W1), 2-stage single-sync cp.async ring (R9)
// ---------------------------------------------------------------------------
#define NSTEP1 24

__global__ __launch_bounds__(256, 2)
void gemm1_mma_kernel(const float* __restrict__ bias)
{
    extern __shared__ __align__(16) char dsm[];
    const uint32_t smem_u32 = (uint32_t)__cvta_generic_to_shared(dsm);

    const int tid  = threadIdx.x;
    const int lane = tid & 31;
    const int w    = tid >> 5;
    const int wm   = w >> 2;
    const int wn   = w & 3;
    const int lq   = lane >> 2;
    const int lr   = lane & 3;
    const int m0   = blockIdx.y * 128;
    const int n0   = blockIdx.x * 128;

    const int lrow0 = tid >> 3;
    const int lch   = tid & 7;

    const int arow  = (lane < 16) ? lane : (lane - 16);
    const int acol8 = (lane < 16) ? 0 : 8;
    uint32_t aoff[4];
#pragma unroll
    for (int mt = 0; mt < 4; mt++)
        aoff[mt] = (uint32_t)(((wm * 64 + mt * 16 + arow) * SPITCH + acol8) * 2);
    const int bg = lane >> 3;
    uint32_t boff[2];
#pragma unroll
    for (int p = 0; p < 2; p++) {
        int nrow = wn * 32 + (2 * p + (bg >> 1)) * 8 + (lane & 7);
        boff[p] = (uint32_t)((nrow * SPITCH + (bg & 1) * 8) * 2);
    }

    auto load_step = [&](int step, int stage) {
        const int phase = step >> 3;
        const int kk    = (step & 7) * 64;
        const __nv_bfloat16* Ag = (phase < 2) ? g_x1 : g_x2;
        const __nv_bfloat16* Bg = (phase == 1) ? g_w2 : g_w1;
        uint32_t sAb = smem_u32 + stage * 2 * STAGE_BYTES;
        uint32_t sBb = sAb + STAGE_BYTES;
#pragma unroll
        for (int i = 0; i < 4; i++) {
            int r = lrow0 + i * 32;
            cp16(sAb + (uint32_t)((r * SPITCH + lch * 8) * 2),
                 Ag + (size_t)(m0 + r) * D_DIM + kk + lch * 8);
            cp16(sBb + (uint32_t)((r * SPITCH + lch * 8) * 2),
                 Bg + (size_t)(n0 + r) * D_DIM + kk + lch * 8);
        }
    };

    float acc[4][4][4];
#pragma unroll
    for (int a = 0; a < 4; a++)
#pragma unroll
        for (int b = 0; b < 4; b++)
#pragma unroll
            for (int c = 0; c < 4; c++) acc[a][b][c] = 0.0f;

    load_step(0, 0);
    CP_COMMIT();

    for (int cur = 0; cur < NSTEP1; cur++) {
        CP_WAIT(0);
        __syncthreads();
        if (cur + 1 < NSTEP1) {
            load_step(cur + 1, (cur + 1) & 1);
            CP_COMMIT();
        }
        const uint32_t sAu = smem_u32 + (uint32_t)((cur & 1) * 2 * STAGE_BYTES);
        const uint32_t sBu = sAu + STAGE_BYTES;
#pragma unroll
        for (int ks = 0; ks < 4; ks++) {
            uint32_t bfr[4][2];
            {
                uint32_t t0[4], t1[4];
                ldsm_x4(t0, sBu + boff[0] + ks * 32);
                ldsm_x4(t1, sBu + boff[1] + ks * 32);
                bfr[0][0] = t0[0]; bfr[0][1] = t0[1];
                bfr[1][0] = t0[2]; bfr[1][1] = t0[3];
                bfr[2][0] = t1[0]; bfr[2][1] = t1[1];
                bfr[3][0] = t1[2]; bfr[3][1] = t1[3];
            }
#pragma unroll
            for (int mt = 0; mt < 4; mt++) {
                uint32_t afr[4];
                ldsm_x4(afr, sAu + aoff[mt] + ks * 32);
#pragma unroll
                for (int nn = 0; nn < 4; nn++)
                    mma16816(acc[mt][nn], afr, bfr[nn]);
            }
        }
    }

    float bia[4][2];
#pragma unroll
    for (int nn = 0; nn < 4; nn++) {
        int col = n0 + wn * 32 + nn * 8 + lr * 2;
        bia[nn][0] = bias[col];
        bia[nn][1] = bias[col + 1];
    }
#pragma unroll
    for (int mt = 0; mt < 4; mt++) {
#pragma unroll
        for (int half = 0; half < 2; half++) {
            const int row = m0 + wm * 64 + mt * 16 + half * 8 + lq;
#pragma unroll
            for (int nn = 0; nn < 4; nn++) {
                const int col = n0 + wn * 32 + nn * 8 + lr * 2;
                float h0 = acc[mt][nn][half * 2 + 0] + bia[nn][0];
                float h1 = acc[mt][nn][half * 2 + 1] + bia[nn][1];
                const size_t o = (size_t)row * D_DIM + col;
                *(float2*)(g_h + o) = make_float2(h0, h1);
                __nv_bfloat16 p0 = __float2bfloat16_rn(h0);
                __nv_bfloat16 p1 = __float2bfloat16_rn(h1);
                __nv_bfloat16 q0 = __float2bfloat16_rn(h0 - __bfloat162float(p0));
                __nv_bfloat16 q1 = __float2bfloat16_rn(h1 - __bfloat162float(p1));
                *(__nv_bfloat162*)(g_hhi + o) = __nv_bfloat162(p0, p1);
                *(__nv_bfloat162*)(g_hlo + o) = __nv_bfloat162(q0, q1);
            }
        }
    }
}

// ---------------------------------------------------------------------------
// GEMM2 pass 1: single-phase bf16, K=512, top-2 + MARGIN1 flag (R9 shape)
// ---------------------------------------------------------------------------
#define NSTEP_P1 128

__global__ __launch_bounds__(256, 2)
void gemm2_pass1_kernel()
{
    extern __shared__ __align__(16) char dsm[];
    const uint32_t smem_u32 = (uint32_t)__cvta_generic_to_shared(dsm);

    const int tid  = threadIdx.x;
    const int lane = tid & 31;
    const int w    = tid >> 5;
    const int wm   = w >> 2;
    const int wn   = w & 3;
    const int lq   = lane >> 2;
    const int lr   = lane & 3;
    const int m0   = blockIdx.x * 128;

    const int lrow0 = tid >> 3;
    const int lch   = tid & 7;

    const int arow  = (lane < 16) ? lane : (lane - 16);
    const int acol8 = (lane < 16) ? 0 : 8;
    uint32_t aoff[4];
#pragma unroll
    for (int mt = 0; mt < 4; mt++)
        aoff[mt] = (uint32_t)(((wm * 64 + mt * 16 + arow) * SPITCH + acol8) * 2);
    const int bg = lane >> 3;
    uint32_t boff[2];
#pragma unroll
    for (int p = 0; p < 2; p++) {
        int nrow = wn * 32 + (2 * p + (bg >> 1)) * 8 + (lane & 7);
        boff[p] = (uint32_t)((nrow * SPITCH + (bg & 1) * 8) * 2);
    }

    float v1[8], v2[8]; int i1[8];
#pragma unroll
    for (int s = 0; s < 8; s++) { v1[s] = 3.4e38f; v2[s] = 3.4e38f; i1[s] = 0; }

#define UPD(sl, cc, ss) do { float _s = (ss); \
    if (_s < v1[sl]) { v2[sl] = v1[sl]; v1[sl] = _s; i1[sl] = (cc); } \
    else if (_s < v2[sl]) v2[sl] = _s; } while (0)

    auto load_step = [&](int step, int stage) {
        const int nt = step >> 3;
        const int kk = (step & 7) * 64;
        const int n0 = nt * 128;
        uint32_t sAb = smem_u32 + stage * 2 * STAGE_BYTES;
        uint32_t sBb = sAb + STAGE_BYTES;
#pragma unroll
        for (int i = 0; i < 4; i++) {
            int r = lrow0 + i * 32;
            cp16(sAb + (uint32_t)((r * SPITCH + lch * 8) * 2),
                 g_hhi + (size_t)(m0 + r) * D_DIM + kk + lch * 8);
            cp16(sBb + (uint32_t)((r * SPITCH + lch * 8) * 2),
                 g_ehi + (size_t)(n0 + r) * D_DIM + kk + lch * 8);
        }
    };

    load_step(0, 0);
    CP_COMMIT();

    float acc[4][4][4];
    for (int nt = 0; nt < 16; nt++) {
        const int n0 = nt * 128;
#pragma unroll
        for (int a = 0; a < 4; a++)
#pragma unroll
            for (int b = 0; b < 4; b++)
#pragma unroll
                for (int c = 0; c < 4; c++) acc[a][b][c] = 0.0f;

        for (int vc = 0; vc < 8; vc++) {
            const int cur = nt * 8 + vc;
            CP_WAIT(0);
            __syncthreads();
            if (cur + 1 < NSTEP_P1) {
                load_step(cur + 1, (cur + 1) & 1);
                CP_COMMIT();
            }
            const uint32_t sAu = smem_u32 + (uint32_t)((cur & 1) * 2 * STAGE_BYTES);
            const uint32_t sBu = sAu + STAGE_BYTES;
#pragma unroll
            for (int ks = 0; ks < 4; ks++) {
                uint32_t bfr[4][2];
                {
                    uint32_t t0[4], t1[4];
                    ldsm_x4(t0, sBu + boff[0] + ks * 32);
                    ldsm_x4(t1, sBu + boff[1] + ks * 32);
                    bfr[0][0] = t0[0]; bfr[0][1] = t0[1];
                    bfr[1][0] = t0[2]; bfr[1][1] = t0[3];
                    bfr[2][0] = t1[0]; bfr[2][1] = t1[1];
                    bfr[3][0] = t1[2]; bfr[3][1] = t1[3];
                }
#pragma unroll
                for (int mt = 0; mt < 4; mt++) {
                    uint32_t afr[4];
                    ldsm_x4(afr, sAu + aoff[mt] + ks * 32);
#pragma unroll
                    for (int nn = 0; nn < 4; nn++)
                        mma16816(acc[mt][nn], afr, bfr[nn]);
                }
            }
        }

#pragma unroll
        for (int mt = 0; mt < 4; mt++) {
#pragma unroll
            for (int nn = 0; nn < 4; nn++) {
                const int col = n0 + wn * 32 + nn * 8 + lr * 2;
                const float e0 = g_en[col], e1 = g_en[col + 1];
                const int s0 = mt * 2, s1 = mt * 2 + 1;
                UPD(s0, col,     e0 - 2.0f * acc[mt][nn][0]);
                UPD(s0, col + 1, e1 - 2.0f * acc[mt][nn][1]);
                UPD(s1, col,     e0 - 2.0f * acc[mt][nn][2]);
                UPD(s1, col + 1, e1 - 2.0f * acc[mt][nn][3]);
            }
        }
    }

#pragma unroll
    for (int off = 1; off <= 2; off <<= 1) {
#pragma unroll
        for (int sl = 0; sl < 8; sl++) {
            float ov1 = __shfl_xor_sync(0xffffffffu, v1[sl], off);
            int   oi1 = __shfl_xor_sync(0xffffffffu, i1[sl], off);
            float ov2 = __shfl_xor_sync(0xffffffffu, v2[sl], off);
            if (ov1 < v1[sl] || (ov1 == v1[sl] && oi1 < i1[sl])) {
                v2[sl] = fminf(v1[sl], ov2); v1[sl] = ov1; i1[sl] = oi1;
            } else {
                v2[sl] = fminf(v2[sl], ov1);
            }
        }
    }

    __syncthreads();
    float* rv1 = (float*)dsm;
    int*   ri1 = (int*)(dsm + 2048);
    float* rv2 = (float*)(dsm + 4096);
    if (lr == 0) {
#pragma unroll
        for (int sl = 0; sl < 8; sl++) {
            int row = wm * 64 + (sl >> 1) * 16 + (sl & 1) * 8 + lq;
            rv1[row * 4 + wn] = v1[sl];
            ri1[row * 4 + wn] = i1[sl];
            rv2[row * 4 + wn] = v2[sl];
        }
    }
    __syncthreads();
    if (tid < 128) {
        float bv1 = rv1[tid * 4]; int bi1 = ri1[tid * 4]; float bv2 = rv2[tid * 4];
#pragma unroll
        for (int j = 1; j < 4; j++) {
            float ov1 = rv1[tid * 4 + j]; int oi1 = ri1[tid * 4 + j]; float ov2 = rv2[tid * 4 + j];
            if (ov1 < bv1 || (ov1 == bv1 && oi1 < bi1)) {
                bv2 = fminf(bv1, ov2); bv1 = ov1; bi1 = oi1;
            } else {
                bv2 = fminf(bv2, ov1);
            }
        }
        const int row = m0 + tid;
        g_idx[row] = bi1;
        if (bv2 - bv1 <= MARGIN1) {
            int slot = atomicAdd(&g_nflag1, 1);
            if (slot < MAXF) g_flag1[slot] = row;
        }
    }
}

// ---------------------------------------------------------------------------
// gather flagged rows
// ---------------------------------------------------------------------------
__global__ __launch_bounds__(128)
void gather_kernel()
{
    const int cnt = min(g_nflag1, MAXF);
    const int tid = threadIdx.x;
    for (int f = blockIdx.x; f < cnt; f += gridDim.x) {
        const int row = g_flag1[f];
        const uint32_t* shi = (const uint32_t*)(g_hhi + (size_t)row * D_DIM);
        const uint32_t* slo = (const uint32_t*)(g_hlo + (size_t)row * D_DIM);
        uint32_t* dhi = (uint32_t*)(g_fhi + (size_t)f * D_DIM);
        uint32_t* dlo = (uint32_t*)(g_flo + (size_t)f * D_DIM);
        dhi[tid * 2] = shi[tid * 2]; dhi[tid * 2 + 1] = shi[tid * 2 + 1];
        dlo[tid * 2] = slo[tid * 2]; dlo[tid * 2 + 1] = slo[tid * 2 + 1];
    }
}

// ---------------------------------------------------------------------------
// pass 2: 3-phase split for flagged rows (R9 shape)
// ---------------------------------------------------------------------------
__global__ __launch_bounds__(256, 2)
void gemm2_pass2_kernel()
{
    const int cnt = min(g_nflag1, MAXF);
    const int rt = blockIdx.x >> 4;
    const int nt = blockIdx.x & 15;
    if (rt * 128 >= cnt) return;

    extern __shared__ __align__(16) char dsm[];
    const uint32_t smem_u32 = (uint32_t)__cvta_generic_to_shared(dsm);

    const int tid  = threadIdx.x;
    const int lane = tid & 31;
    const int w    = tid >> 5;
    const int wm   = w >> 2;
    const int wn   = w & 3;
    const int lq   = lane >> 2;
    const int lr   = lane & 3;
    const int f0   = rt * 128;
    const int n0   = nt * 128;

    const int lrow0 = tid >> 3;
    const int lch   = tid & 7;

    const int arow  = (lane < 16) ? lane : (lane - 16);
    const int acol8 = (lane < 16) ? 0 : 8;
    uint32_t aoff[4];
#pragma unroll
    for (int mt = 0; mt < 4; mt++)
        aoff[mt] = (uint32_t)(((wm * 64 + mt * 16 + arow) * SPITCH + acol8) * 2);
    const int bg = lane >> 3;
    uint32_t boff[2];
#pragma unroll
    for (int p = 0; p < 2; p++) {
        int nrow = wn * 32 + (2 * p + (bg >> 1)) * 8 + (lane & 7);
        boff[p] = (uint32_t)((nrow * SPITCH + (bg & 1) * 8) * 2);
    }

    auto load_step = [&](int step, int stage) {
        const int phase = step >> 3;
        const int kk    = (step & 7) * 64;
        const __nv_bfloat16* Ag = (phase < 2)  ? g_fhi : g_flo;
        const __nv_bfloat16* Bg = (phase == 1) ? g_elo : g_ehi;
        uint32_t sAb = smem_u32 + stage * 2 * STAGE_BYTES;
        uint32_t sBb = sAb + STAGE_BYTES;
#pragma unroll
        for (int i = 0; i < 4; i++) {
            int r = lrow0 + i * 32;
            cp16(sAb + (uint32_t)((r * SPITCH + lch * 8) * 2),
                 Ag + (size_t)(f0 + r) * D_DIM + kk + lch * 8);
            cp16(sBb + (uint32_t)((r * SPITCH + lch * 8) * 2),
                 Bg + (size_t)(n0 + r) * D_DIM + kk + lch * 8);
        }
    };

    float acc[4][4][4];
#pragma unroll
    for (int a = 0; a < 4; a++)
#pragma unroll
        for (int b = 0; b < 4; b++)
#pragma unroll
            for (int c = 0; c < 4; c++) acc[a][b][c] = 0.0f;

    load_step(0, 0);
    CP_COMMIT();

    for (int cur = 0; cur < 24; cur++) {
        CP_WAIT(0);
        __syncthreads();
        if (cur + 1 < 24) {
            load_step(cur + 1, (cur + 1) & 1);
            CP_COMMIT();
        }
        const uint32_t sAu = smem_u32 + (uint32_t)((cur & 1) * 2 * STAGE_BYTES);
        const uint32_t sBu = sAu + STAGE_BYTES;
#pragma unroll
        for (int ks = 0; ks < 4; ks++) {
            uint32_t bfr[4][2];
            {
                uint32_t t0[4], t1[4];
                ldsm_x4(t0, sBu + boff[0] + ks * 32);
                ldsm_x4(t1, sBu + boff[1] + ks * 32);
                bfr[0][0] = t0[0]; bfr[0][1] = t0[1];
                bfr[1][0] = t0[2]; bfr[1][1] = t0[3];
                bfr[2][0] = t1[0]; bfr[2][1] = t1[1];
                bfr[3][0] = t1[2]; bfr[3][1] = t1[3];
            }
#pragma unroll
            for (int mt = 0; mt < 4; mt++) {
                uint32_t afr[4];
                ldsm_x4(afr, sAu + aoff[mt] + ks * 32);
#pragma unroll
                for (int nn = 0; nn < 4; nn++)
                    mma16816(acc[mt][nn], afr, bfr[nn]);
            }
        }
    }

    float v1[8], v2[8]; int i1[8];
#pragma unroll
    for (int s = 0; s < 8; s++) { v1[s] = 3.4e38f; v2[s] = 3.4e38f; i1[s] = 0; }
#pragma unroll
    for (int mt = 0; mt < 4; mt++) {
#pragma unroll
        for (int nn = 0; nn < 4; nn++) {
            const int col = n0 + wn * 32 + nn * 8 + lr * 2;
            const float e0 = g_en[col], e1 = g_en[col + 1];
            const int s0 = mt * 2, s1 = mt * 2 + 1;
            UPD(s0, col,     e0 - 2.0f * acc[mt][nn][0]);
            UPD(s0, col + 1, e1 - 2.0f * acc[mt][nn][1]);
            UPD(s1, col,     e0 - 2.0f * acc[mt][nn][2]);
            UPD(s1, col + 1, e1 - 2.0f * acc[mt][nn][3]);
        }
    }

#pragma unroll
    for (int off = 1; off <= 2; off <<= 1) {
#pragma unroll
        for (int sl = 0; sl < 8; sl++) {
            float ov1 = __shfl_xor_sync(0xffffffffu, v1[sl], off);
            int   oi1 = __shfl_xor_sync(0xffffffffu, i1[sl], off);
            float ov2 = __shfl_xor_sync(0xffffffffu, v2[sl], off);
            if (ov1 < v1[sl] || (ov1 == v1[sl] && oi1 < i1[sl])) {
                v2[sl] = fminf(v1[sl], ov2); v1[sl] = ov1; i1[sl] = oi1;
            } else {
                v2[sl] = fminf(v2[sl], ov1);
            }
        }
    }

    __syncthreads();
    float* rv1 = (float*)dsm;
    int*   ri1 = (int*)(dsm + 2048);
    float* rv2 = (float*)(dsm + 4096);
    if (lr == 0) {
#pragma unroll
        for (int sl = 0; sl < 8; sl++) {
            int row = wm * 64 + (sl >> 1) * 16 + (sl & 1) * 8 + lq;
            rv1[row * 4 + wn] = v1[sl];
            ri1[row * 4 + wn] = i1[sl];
            rv2[row * 4 + wn] = v2[sl];
        }
    }
    __syncthreads();
    if (tid < 128) {
        float bv1 = rv1[tid * 4]; int bi1 = ri1[tid * 4]; float bv2 = rv2[tid * 4];
#pragma unroll
        for (int j = 1; j < 4; j++) {
            float ov1 = rv1[tid * 4 + j]; int oi1 = ri1[tid * 4 + j]; float ov2 = rv2[tid * 4 + j];
            if (ov1 < bv1 || (ov1 == bv1 && oi1 < bi1)) {
                bv2 = fminf(bv1, ov2); bv1 = ov1; bi1 = oi1;
            } else {
                bv2 = fminf(bv2, ov1);
            }
        }
        const int crow = f0 + tid;
        g_p2k[(size_t)crow * 16 + nt] =
            ((unsigned long long)fmap(bv1) << 32) | (unsigned)bi1;
        g_p2v[(size_t)crow * 16 + nt] = bv2;
    }
}

// ---------------------------------------------------------------------------
// combine
// ---------------------------------------------------------------------------
__global__ __launch_bounds__(256)
void combine_kernel()
{
    const int cnt = min(g_nflag1, MAXF);
    for (int f = blockIdx.x * 256 + threadIdx.x; f < cnt; f += gridDim.x * 256) {
        unsigned long long bestk = 0xFFFFFFFFFFFFFFFFull;
#pragma unroll
        for (int j = 0; j < 16; j++)
            bestk = min(bestk, g_p2k[(size_t)f * 16 + j]);
        float s1 = funmap((uint32_t)(bestk >> 32));
        float s2 = 3.4e38f;
#pragma unroll
        for (int j = 0; j < 16; j++) {
            unsigned long long k = g_p2k[(size_t)f * 16 + j];
            float v2 = g_p2v[(size_t)f * 16 + j];
            if (k != bestk) s2 = fminf(s2, funmap((uint32_t)(k >> 32)));
            s2 = fminf(s2, v2);
        }
        const int orig = g_flag1[f];
        if (s2 - s1 <= MARGIN2) {
            g_idx[orig]  = -1;
            g_best[orig] = 0xFFFFFFFFFFFFFFFFull;
            int slot = atomicAdd(&g_nflag, 1);
            g_flagged[slot] = orig;
        } else {
            g_idx[orig] = (int)(bestk & 0xFFFFFFFFull);
        }
    }
}

// ---------------------------------------------------------------------------
// Exact fp32 fallback
// ---------------------------------------------------------------------------
__global__ __launch_bounds__(256)
void fallback_kernel(const float* __restrict__ emb)
{
    __shared__ float hrow[D_DIM];
    const int tid = threadIdx.x;
    const int cnt = g_nflag;
    const int total = cnt * 8;

    for (int wk = blockIdx.x; wk < total; wk += gridDim.x) {
        const int f     = wk >> 3;
        const int chunk = wk & 7;
        const int row   = g_flagged[f];

        if (tid < 128)
            *(float4*)(hrow + tid * 4) = *(const float4*)(g_h + (size_t)row * D_DIM + tid * 4);
        __syncthreads();

        const int k = chunk * 256 + tid;
        const float4* ep = (const float4*)(emb + (size_t)k * D_DIM);
        float a0 = 0.f, a1 = 0.f, a2 = 0.f, a3 = 0.f;
#pragma unroll 16
        for (int d4 = 0; d4 < D_DIM / 4; d4++) {
            float4 e = ep[d4];
            float4 h = *(const float4*)(hrow + d4 * 4);
            a0 += e.x * h.x; a1 += e.y * h.y; a2 += e.z * h.z; a3 += e.w * h.w;
        }
        float s = g_en[k] - 2.0f * ((a0 + a1) + (a2 + a3));
        unsigned long long key = ((unsigned long long)fmap(s) << 32) | (unsigned)k;
        atomicMin(&g_best[row], key);
        __syncthreads();
    }
}

// ---------------------------------------------------------------------------
// Epilogue
// ---------------------------------------------------------------------------
__global__ void epilogue_kernel(const float* __restrict__ emb, float* __restrict__ out)
{
    __shared__ float red[128];
    const int n   = blockIdx.x;
    const int tid = threadIdx.x;
    int idx = g_idx[n];
    if (idx < 0) idx = (int)(g_best[n] & 0xFFFFFFFFull);

    float4 hv = *(const float4*)(g_h + (size_t)n * D_DIM + tid * 4);
    float4 qv = *(const float4*)(emb + (size_t)idx * D_DIM + tid * 4);
    float d0 = qv.x - hv.x, d1 = qv.y - hv.y, d2 = qv.z - hv.z, d3 = qv.w - hv.w;

    float* qo = out + OFF_QOUT + (size_t)n * D_DIM + tid * 4;
    __stcs(qo + 0, hv.x + d0);
    __stcs(qo + 1, hv.y + d1);
    __stcs(qo + 2, hv.z + d2);
    __stcs(qo + 3, hv.w + d3);

    red[tid] = d0 * d0 + d1 * d1 + d2 * d2 + d3 * d3;

    float2* er2 = (float2*)(out + OFF_ENC + (size_t)n * K_CODES);
    const int unit = idx >> 1, comp = idx & 1;
#pragma unroll
    for (int i = 0; i < 8; i++) {
        int u = tid + i * 128;
        float2 v = make_float2(0.0f, 0.0f);
        if (u == unit) { if (comp == 0) v.x = 1.0f; else v.y = 1.0f; }
        __stcs(er2 + u, v);
    }

    __syncthreads();
    for (int off = 64; off; off >>= 1) {
        if (tid < off) red[tid] += red[tid + off];
        __syncthreads();
    }
    if (tid == 0) {
        g_partial[n] = red[0];
        atomicAdd(&g_counts[idx], 1);
    }
}

// ---------------------------------------------------------------------------
__global__ void final_kernel(float* __restrict__ out)
{
    __shared__ float red[1024];
    const int tid = threadIdx.x;

    float s = 0.0f;
    for (int i = 0; i < N_ROWS / 1024; i++) s += g_partial[tid + i * 1024];
    red[tid] = s;
    __syncthreads();
    for (int off = 512; off; off >>= 1) {
        if (tid < off) red[tid] += red[tid + off];
        __syncthreads();
    }
    if (tid == 0) out[0] = 0.25f * red[0] / (float)((size_t)N_ROWS * D_DIM);
    __syncthreads();

    float p = 0.0f;
    for (int i = 0; i < K_CODES / 1024; i++) {
        float c  = (float)g_counts[tid + i * 1024];
        float pr = c * (1.0f / (float)N_ROWS);
        p += pr * logf(pr + 1e-10f);
    }
    red[tid] = p;
    __syncthreads();
    for (int off = 512; off; off >>= 1) {
        if (tid < off) red[tid] += red[tid + off];
        __syncthreads();
    }
    if (tid == 0) out[OFF_PERP] = expf(-red[0]);
}

// ---------------------------------------------------------------------------
extern "C" void kernel_launch(void* const* d_in, const int* in_sizes, int n_in,
                              void* d_out, int out_size)
{
    const float *x0 = nullptr, *x1 = nullptr, *W = nullptr, *b = nullptr, *emb = nullptr;
    for (int i = 0; i < n_in; i++) {
        const float* p = (const float*)d_in[i];
        const long long s = in_sizes[i];
        if (s == (long long)N_ROWS * HALFW)       { if (!x0) x0 = p; else x1 = p; }
        else if (s == (long long)D_DIM * D_DIM)   W = p;
        else if (s == (long long)D_DIM)           b = p;
        else if (s == (long long)K_CODES * D_DIM) emb = p;
    }
    float* out = (float*)d_out;

    static int smem_set = 0;
    if (!smem_set) {
        cudaFuncSetAttribute(gemm1_mma_kernel,
                             cudaFuncAttributeMaxDynamicSharedMemorySize, RING_BYTES);
        cudaFuncSetAttribute(gemm2_pass1_kernel,
                             cudaFuncAttributeMaxDynamicSharedMemorySize, RING_BYTES);
        cudaFuncSetAttribute(gemm2_pass2_kernel,
                             cudaFuncAttributeMaxDynamicSharedMemorySize, RING_BYTES);
        smem_set = 1;
    }

    prep_xw_kernel<<<(N_ROWS * D_DIM) / 1024 + (D_DIM * D_DIM) / 1024, 256>>>(x0, x1, W);
    prep_emb_kernel<<<K_CODES, 128>>>(emb);
    gemm1_mma_kernel<<<dim3(D_DIM / 128, N_ROWS / 128), 256, RING_BYTES>>>(b);
    gemm2_pass1_kernel<<<N_ROWS / 128, 256, RING_BYTES>>>();
    gather_kernel<<<1024, 128>>>();
    gemm2_pass2_kernel<<<(MAXF / 128) * 16, 256, RING_BYTES>>>();
    combine_kernel<<<32, 256>>>();
    fallback_kernel<<<2048, 256>>>(emb);
    epilogue_kernel<<<N_ROWS, 128>>>(emb, out);
    final_kernel<<<1, 1024>>>(out);
}